// round 11
// baseline (speedup 1.0000x reference)
#include <cuda_runtime.h>
#include <cuda_bf16.h>
#include <cstdint>

#define N_NODES 50000
#define D 128
#define TM 32
#define SCAN_BS 1024
#define SCAN_NB ((N_NODES + SCAN_BS - 1) / SCAN_BS)   // 49
#define P2 264   // padded row stride (bf16 elems) for K=256 tiles
#define P1 136   // padded row stride for K=128 tiles

// ---- scratch (allocation-free: __device__ globals) ----
__device__ float g_agg[(size_t)N_NODES * D];   // mean-aggregated features
__device__ float g_h1 [(size_t)N_NODES * D];
__device__ float g_h2 [(size_t)N_NODES * D];
__device__ float g_inv[N_NODES];
__device__ int   g_cnt[N_NODES];
__device__ int   g_scan[N_NODES];
__device__ int   g_rowptr[N_NODES + 1];
__device__ int   g_cursor[N_NODES];
__device__ int   g_eidx[1700000];              // src node per CSR slot (E <= 1.6M)
__device__ int   g_bsum[SCAN_NB];

// ================= CSR build =================
__global__ void k_zero_cnt() {
    int i = blockIdx.x * blockDim.x + threadIdx.x;
    if (i < N_NODES) g_cnt[i] = 0;
}

// edge_index is int32 on device: layout [2, E] row-major.
__global__ void k_count(const int* __restrict__ ei, int E) {
    int e = blockIdx.x * blockDim.x + threadIdx.x;
    if (e < E) atomicAdd(&g_cnt[ei[E + e]], 1);
}

__global__ void k_scan1() {
    __shared__ int sh[SCAN_BS];
    int i = blockIdx.x * SCAN_BS + threadIdx.x;
    int v = (i < N_NODES) ? g_cnt[i] : 0;
    sh[threadIdx.x] = v;
    __syncthreads();
    for (int off = 1; off < SCAN_BS; off <<= 1) {
        int t = (threadIdx.x >= off) ? sh[threadIdx.x - off] : 0;
        __syncthreads();
        sh[threadIdx.x] += t;
        __syncthreads();
    }
    if (i < N_NODES) g_scan[i] = sh[threadIdx.x];
    if (threadIdx.x == SCAN_BS - 1) g_bsum[blockIdx.x] = sh[threadIdx.x];
}

// merged: per-block exclusive prefix of bsum computed locally, then finalize
__global__ void k_scan23() {
    __shared__ int pre[SCAN_NB];
    if (threadIdx.x < SCAN_NB) pre[threadIdx.x] = g_bsum[threadIdx.x];
    __syncthreads();
    if (threadIdx.x == 0) {
        int run = 0;
        #pragma unroll 1
        for (int b = 0; b < SCAN_NB; b++) { int v = pre[b]; pre[b] = run; run += v; }
    }
    __syncthreads();
    int i = blockIdx.x * blockDim.x + threadIdx.x;
    if (i < N_NODES) {
        int incl = g_scan[i] + pre[i / SCAN_BS];
        int cnt  = g_cnt[i];
        int excl = incl - cnt;
        g_rowptr[i] = excl;
        g_cursor[i] = excl;
        g_inv[i]    = 1.0f / fmaxf((float)cnt, 1.0f);
        if (i == N_NODES - 1) g_rowptr[N_NODES] = incl;
    }
}

__global__ void k_fill(const int* __restrict__ ei, int E) {
    int e = blockIdx.x * blockDim.x + threadIdx.x;
    if (e < E) {
        int src = ei[e];
        int dst = ei[E + e];
        int pos = atomicAdd(&g_cursor[dst], 1);
        g_eidx[pos] = src;
    }
}

// ================= gather-mean (no atomics, fp32 — known good) =================
__global__ __launch_bounds__(256)
void k_gather(const float* __restrict__ xext, int layer) {
    const float* feat = (layer == 0) ? xext : g_h1;
    int lane = threadIdx.x & 31;
    int node = blockIdx.x * 8 + (threadIdx.x >> 5);
    if (node >= N_NODES) return;

    int b = g_rowptr[node];
    int e = g_rowptr[node + 1];
    float4 acc = make_float4(0.f, 0.f, 0.f, 0.f);

    int j = b;
    for (; j + 4 <= e; j += 4) {
        int s0 = g_eidx[j + 0], s1 = g_eidx[j + 1];
        int s2 = g_eidx[j + 2], s3 = g_eidx[j + 3];
        float4 v0 = __ldg((const float4*)(feat + (size_t)s0 * D) + lane);
        float4 v1 = __ldg((const float4*)(feat + (size_t)s1 * D) + lane);
        float4 v2 = __ldg((const float4*)(feat + (size_t)s2 * D) + lane);
        float4 v3 = __ldg((const float4*)(feat + (size_t)s3 * D) + lane);
        acc.x += (v0.x + v1.x) + (v2.x + v3.x);
        acc.y += (v0.y + v1.y) + (v2.y + v3.y);
        acc.z += (v0.z + v1.z) + (v2.z + v3.z);
        acc.w += (v0.w + v1.w) + (v2.w + v3.w);
    }
    for (; j < e; j++) {
        int s = g_eidx[j];
        float4 v = __ldg((const float4*)(feat + (size_t)s * D) + lane);
        acc.x += v.x; acc.y += v.y; acc.z += v.z; acc.w += v.w;
    }
    float sc = g_inv[node];
    acc.x *= sc; acc.y *= sc; acc.z *= sc; acc.w *= sc;
    ((float4*)(g_agg + (size_t)node * D))[lane] = acc;
}

// ---- fast packed bf16 hi/lo split of a float4, 8B smem stores ----
__device__ __forceinline__ void split4_store(__nv_bfloat16* hi_base,
                                             __nv_bfloat16* lo_base,
                                             int off, float4 v) {
    uint32_t h01, h23, l01, l23;
    asm("cvt.rn.bf16x2.f32 %0, %1, %2;" : "=r"(h01) : "f"(v.y), "f"(v.x));
    asm("cvt.rn.bf16x2.f32 %0, %1, %2;" : "=r"(h23) : "f"(v.w), "f"(v.z));
    float hx = __uint_as_float(h01 << 16);
    float hy = __uint_as_float(h01 & 0xffff0000u);
    float hz = __uint_as_float(h23 << 16);
    float hw = __uint_as_float(h23 & 0xffff0000u);
    asm("cvt.rn.bf16x2.f32 %0, %1, %2;" : "=r"(l01) : "f"(v.y - hy), "f"(v.x - hx));
    asm("cvt.rn.bf16x2.f32 %0, %1, %2;" : "=r"(l23) : "f"(v.w - hw), "f"(v.z - hz));
    *(uint2*)(hi_base + off) = make_uint2(h01, h23);
    *(uint2*)(lo_base + off) = make_uint2(l01, l23);
}

#define MMA_BF16(C, A0, A1, A2, A3, B0, B1)                                    \
    asm volatile(                                                              \
        "mma.sync.aligned.m16n8k16.row.col.f32.bf16.bf16.f32 "                 \
        "{%0,%1,%2,%3}, {%4,%5,%6,%7}, {%8,%9}, {%0,%1,%2,%3};"                \
        : "+f"((C)[0]), "+f"((C)[1]), "+f"((C)[2]), "+f"((C)[3])               \
        : "r"(A0), "r"(A1), "r"(A2), "r"(A3), "r"(B0), "r"(B1))

// ================= fused SAGE layer (tensor core, bf16 3-term split) =========
// out = relu( [agg|xroot](50000x256) @ [wl;wr]^T + bl )
__global__ __launch_bounds__(256, 1)
void k_sage_mma(const float* __restrict__ xext,
                const float* __restrict__ wl, const float* __restrict__ bl,
                const float* __restrict__ wr, int layer) {
    extern __shared__ __nv_bfloat16 sm[];
    __nv_bfloat16* sB_hi = sm;                       // 128 * P2
    __nv_bfloat16* sB_lo = sB_hi + 128 * P2;
    __nv_bfloat16* sA_hi = sB_lo + 128 * P2;         // 32 * P2
    __nv_bfloat16* sA_lo = sA_hi + 32 * P2;

    const float* xroot = (layer == 0) ? xext : g_h1;
    float* out = (layer == 0) ? g_h1 : g_h2;

    const int tid  = threadIdx.x;
    const int lane = tid & 31;
    const int w    = tid >> 5;
    const int g    = lane >> 2;
    const int q    = lane & 3;
    const int mr   = (w & 1) * 16;     // warp row offset within 32-row tile
    const int n0   = (w >> 1) * 32;    // warp col offset (4 n8-tiles)

    // stage weights (hi/lo split): B[n][k], K=256 = [wl | wr], float4 path
    for (int idx = tid; idx < 128 * 64; idx += 256) {
        int n  = idx >> 6;
        int k4 = (idx & 63) * 4;
        float4 v = (k4 < 128) ? *(const float4*)&wl[n * 128 + k4]
                              : *(const float4*)&wr[n * 128 + (k4 - 128)];
        split4_store(sB_hi, sB_lo, n * P2 + k4, v);
    }
    float2 bias_t[4];
    #pragma unroll
    for (int t = 0; t < 4; t++)
        bias_t[t] = *(const float2*)&bl[n0 + t * 8 + q * 2];
    __syncthreads();

    const int ntiles = (N_NODES + TM - 1) / TM;
    for (int tile = blockIdx.x; tile < ntiles; tile += gridDim.x) {
        const int row0 = tile * TM;
        __syncthreads();
        // stage A tile (32 x 256): [agg | xroot], hi/lo split, float4 path
        #pragma unroll 2
        for (int idx = tid; idx < TM * 64; idx += 256) {
            int r  = idx >> 6;
            int k4 = (idx & 63) * 4;
            int grow = row0 + r;
            float4 v = make_float4(0.f, 0.f, 0.f, 0.f);
            if (grow < N_NODES)
                v = (k4 < 128)
                    ? *(const float4*)&g_agg[(size_t)grow * D + k4]
                    : __ldg((const float4*)&xroot[(size_t)grow * D + (k4 - 128)]);
            split4_store(sA_hi, sA_lo, r * P2 + k4, v);
        }
        __syncthreads();

        float acc[4][4];
        #pragma unroll
        for (int t = 0; t < 4; t++)
            #pragma unroll
            for (int c = 0; c < 4; c++) acc[t][c] = 0.f;

        #pragma unroll 4
        for (int ks = 0; ks < 16; ks++) {
            const int kk = ks * 16 + q * 2;
            const int ra = (mr + g) * P2;
            uint32_t ah0 = *(const uint32_t*)&sA_hi[ra + kk];
            uint32_t ah1 = *(const uint32_t*)&sA_hi[ra + 8 * P2 + kk];
            uint32_t ah2 = *(const uint32_t*)&sA_hi[ra + kk + 8];
            uint32_t ah3 = *(const uint32_t*)&sA_hi[ra + 8 * P2 + kk + 8];
            uint32_t al0 = *(const uint32_t*)&sA_lo[ra + kk];
            uint32_t al1 = *(const uint32_t*)&sA_lo[ra + 8 * P2 + kk];
            uint32_t al2 = *(const uint32_t*)&sA_lo[ra + kk + 8];
            uint32_t al3 = *(const uint32_t*)&sA_lo[ra + 8 * P2 + kk + 8];
            #pragma unroll
            for (int t = 0; t < 4; t++) {
                const int nb = (n0 + t * 8 + g) * P2;
                uint32_t bh0 = *(const uint32_t*)&sB_hi[nb + kk];
                uint32_t bh1 = *(const uint32_t*)&sB_hi[nb + kk + 8];
                uint32_t bl0_ = *(const uint32_t*)&sB_lo[nb + kk];
                uint32_t bl1_ = *(const uint32_t*)&sB_lo[nb + kk + 8];
                MMA_BF16(acc[t], ah0, ah1, ah2, ah3, bh0, bh1);
                MMA_BF16(acc[t], ah0, ah1, ah2, ah3, bl0_, bl1_);
                MMA_BF16(acc[t], al0, al1, al2, al3, bh0, bh1);
            }
        }

        // epilogue: bias + relu, f32 store
        const int rA = row0 + mr + g;
        const int rB = rA + 8;
        #pragma unroll
        for (int t = 0; t < 4; t++) {
            const int col0 = n0 + t * 8 + q * 2;
            if (rA < N_NODES) {
                float2 o;
                o.x = fmaxf(acc[t][0] + bias_t[t].x, 0.f);
                o.y = fmaxf(acc[t][1] + bias_t[t].y, 0.f);
                *(float2*)&out[(size_t)rA * D + col0] = o;
            }
            if (rB < N_NODES) {
                float2 o;
                o.x = fmaxf(acc[t][2] + bias_t[t].x, 0.f);
                o.y = fmaxf(acc[t][3] + bias_t[t].y, 0.f);
                *(float2*)&out[(size_t)rB * D + col0] = o;
            }
        }
    }
}

// ================= fused MLP head (tensor core) =================
// h3 = relu(g_h2 @ mw1^T + mb1);  out = h3 @ mw2^T + mb2   -> [N]
__global__ __launch_bounds__(256, 2)
void k_mlp_mma(const float* __restrict__ mw1, const float* __restrict__ mb1,
               const float* __restrict__ mw2, const float* __restrict__ mb2,
               float* __restrict__ out) {
    extern __shared__ __nv_bfloat16 sm[];
    __nv_bfloat16* sB_hi = sm;                       // 128 * P1
    __nv_bfloat16* sB_lo = sB_hi + 128 * P1;
    __nv_bfloat16* sA_hi = sB_lo + 128 * P1;         // 32 * P1
    __nv_bfloat16* sA_lo = sA_hi + 32 * P1;
    float* s_part = (float*)(sA_lo + 32 * P1);       // [4][32]

    const int tid  = threadIdx.x;
    const int lane = tid & 31;
    const int w    = tid >> 5;
    const int g    = lane >> 2;
    const int q    = lane & 3;
    const int mr   = (w & 1) * 16;
    const int n0   = (w >> 1) * 32;
    const int grp  = w >> 1;

    for (int idx = tid; idx < 128 * 32; idx += 256) {
        int n  = idx >> 5;
        int k4 = (idx & 31) * 4;
        float4 v = *(const float4*)&mw1[n * 128 + k4];
        split4_store(sB_hi, sB_lo, n * P1 + k4, v);
    }
    float2 b1_t[4], w2_t[4];
    #pragma unroll
    for (int t = 0; t < 4; t++) {
        b1_t[t] = *(const float2*)&mb1[n0 + t * 8 + q * 2];
        w2_t[t] = *(const float2*)&mw2[n0 + t * 8 + q * 2];
    }
    const float b2 = mb2[0];
    __syncthreads();

    const int ntiles = (N_NODES + TM - 1) / TM;
    for (int tile = blockIdx.x; tile < ntiles; tile += gridDim.x) {
        const int row0 = tile * TM;
        __syncthreads();
        #pragma unroll 2
        for (int idx = tid; idx < TM * 32; idx += 256) {
            int r  = idx >> 5;
            int k4 = (idx & 31) * 4;
            int grow = row0 + r;
            float4 v = (grow < N_NODES)
                ? *(const float4*)&g_h2[(size_t)grow * D + k4]
                : make_float4(0.f, 0.f, 0.f, 0.f);
            split4_store(sA_hi, sA_lo, r * P1 + k4, v);
        }
        __syncthreads();

        float acc[4][4];
        #pragma unroll
        for (int t = 0; t < 4; t++)
            #pragma unroll
            for (int c = 0; c < 4; c++) acc[t][c] = 0.f;

        #pragma unroll 4
        for (int ks = 0; ks < 8; ks++) {
            const int kk = ks * 16 + q * 2;
            const int ra = (mr + g) * P1;
            uint32_t ah0 = *(const uint32_t*)&sA_hi[ra + kk];
            uint32_t ah1 = *(const uint32_t*)&sA_hi[ra + 8 * P1 + kk];
            uint32_t ah2 = *(const uint32_t*)&sA_hi[ra + kk + 8];
            uint32_t ah3 = *(const uint32_t*)&sA_hi[ra + 8 * P1 + kk + 8];
            uint32_t al0 = *(const uint32_t*)&sA_lo[ra + kk];
            uint32_t al1 = *(const uint32_t*)&sA_lo[ra + 8 * P1 + kk];
            uint32_t al2 = *(const uint32_t*)&sA_lo[ra + kk + 8];
            uint32_t al3 = *(const uint32_t*)&sA_lo[ra + 8 * P1 + kk + 8];
            #pragma unroll
            for (int t = 0; t < 4; t++) {
                const int nb = (n0 + t * 8 + g) * P1;
                uint32_t bh0 = *(const uint32_t*)&sB_hi[nb + kk];
                uint32_t bh1 = *(const uint32_t*)&sB_hi[nb + kk + 8];
                uint32_t bl0_ = *(const uint32_t*)&sB_lo[nb + kk];
                uint32_t bl1_ = *(const uint32_t*)&sB_lo[nb + kk + 8];
                MMA_BF16(acc[t], ah0, ah1, ah2, ah3, bh0, bh1);
                MMA_BF16(acc[t], ah0, ah1, ah2, ah3, bl0_, bl1_);
                MMA_BF16(acc[t], al0, al1, al2, al3, bh0, bh1);
            }
        }

        // head: relu then dot with mw2 over this warp's 32 cols
        float pg = 0.f, pg8 = 0.f;
        #pragma unroll
        for (int t = 0; t < 4; t++) {
            pg  += fmaxf(acc[t][0] + b1_t[t].x, 0.f) * w2_t[t].x
                 + fmaxf(acc[t][1] + b1_t[t].y, 0.f) * w2_t[t].y;
            pg8 += fmaxf(acc[t][2] + b1_t[t].x, 0.f) * w2_t[t].x
                 + fmaxf(acc[t][3] + b1_t[t].y, 0.f) * w2_t[t].y;
        }
        pg  += __shfl_xor_sync(0xffffffffu, pg, 1);
        pg  += __shfl_xor_sync(0xffffffffu, pg, 2);
        pg8 += __shfl_xor_sync(0xffffffffu, pg8, 1);
        pg8 += __shfl_xor_sync(0xffffffffu, pg8, 2);
        if (q == 0) {
            s_part[grp * 32 + mr + g]     = pg;
            s_part[grp * 32 + mr + g + 8] = pg8;
        }
        __syncthreads();
        if (tid < 32) {
            int grow = row0 + tid;
            if (grow < N_NODES) {
                out[grow] = s_part[tid] + s_part[32 + tid] + s_part[64 + tid]
                          + s_part[96 + tid] + b2;
            }
        }
    }
}

extern "C" void kernel_launch(void* const* d_in, const int* in_sizes, int n_in,
                              void* d_out, int out_size) {
    const float* x   = (const float*)d_in[0];
    const int*   ei  = (const int*)d_in[1];      // int32 (JAX x64 disabled)
    const float* w1l = (const float*)d_in[2];
    const float* b1l = (const float*)d_in[3];
    const float* w1r = (const float*)d_in[4];
    const float* w2l = (const float*)d_in[5];
    const float* b2l = (const float*)d_in[6];
    const float* w2r = (const float*)d_in[7];
    const float* mw1 = (const float*)d_in[8];
    const float* mb1 = (const float*)d_in[9];
    const float* mw2 = (const float*)d_in[10];
    const float* mb2 = (const float*)d_in[11];
    float* out = (float*)d_out;
    const int E = in_sizes[1] / 2;

    const int sage_smem = (2 * 128 * P2 + 2 * 32 * P2) * (int)sizeof(__nv_bfloat16); // 168960
    const int mlp_smem  = (2 * 128 * P1 + 2 * 32 * P1) * (int)sizeof(__nv_bfloat16)
                        + 4 * 32 * (int)sizeof(float);                               // 87552
    cudaFuncSetAttribute(k_sage_mma, cudaFuncAttributeMaxDynamicSharedMemorySize, sage_smem);
    cudaFuncSetAttribute(k_mlp_mma,  cudaFuncAttributeMaxDynamicSharedMemorySize, mlp_smem);

    // ---- CSR build ----
    k_zero_cnt<<<(N_NODES + 255) / 256, 256>>>();              // launch 1
    k_count<<<(E + 255) / 256, 256>>>(ei, E);                  // launch 2
    k_scan1<<<SCAN_NB, SCAN_BS>>>();                           // launch 3

    // launch 4 — PROFILING DUMMY: ncu's fixed skip-count lands here every round.
    // Reads stale g_agg (deterministic across replays); writes g_h1 which the
    // real layer-1 sage below fully overwrites. Gives us a real SAGE profile.
    k_sage_mma<<<148, 256, sage_smem>>>(x, w1l, b1l, w1r, 0);  // launch 4 (dummy)

    k_scan23<<<(N_NODES + 255) / 256, 256>>>();                // launch 5
    k_fill<<<(E + 255) / 256, 256>>>(ei, E);                   // launch 6

    const int gat_blocks = (N_NODES + 7) / 8;

    // ---- layer 1 ----
    k_gather<<<gat_blocks, 256>>>(x, 0);                       // launch 7
    k_sage_mma<<<148, 256, sage_smem>>>(x, w1l, b1l, w1r, 0);  // launch 8

    // ---- layer 2 ----
    k_gather<<<gat_blocks, 256>>>(x, 1);                       // launch 9
    k_sage_mma<<<148, 256, sage_smem>>>(x, w2l, b2l, w2r, 1);  // launch 10

    // ---- MLP head ----
    k_mlp_mma<<<296, 256, mlp_smem>>>(mw1, mb1, mw2, mb2, out); // launch 11
}

// round 12
// speedup vs baseline: 1.2019x; 1.2019x over previous
#include <cuda_runtime.h>
#include <cuda_bf16.h>
#include <cstdint>

#define N_NODES 50000
#define D 128
#define TM 32
#define NTILES ((N_NODES + TM - 1) / TM)   // 1563
#define SCAN_BS 1024
#define SCAN_NB ((N_NODES + SCAN_BS - 1) / SCAN_BS)   // 49
#define P2 264   // padded row stride (bf16 elems) for K=256 tiles
#define P1 136   // padded row stride for K=128 tiles

// ---- scratch (allocation-free: __device__ globals) ----
__device__ float g_agg[(size_t)N_NODES * D];   // mean-aggregated features
__device__ float g_h1 [(size_t)N_NODES * D];
__device__ float g_h2 [(size_t)N_NODES * D];
__device__ float g_inv[N_NODES];
__device__ int   g_cnt[N_NODES];
__device__ int   g_scan[N_NODES];
__device__ int   g_rowptr[N_NODES + 1];
__device__ int   g_cursor[N_NODES];
__device__ int   g_eidx[1700000];              // src node per CSR slot (E <= 1.6M)
__device__ int   g_bsum[SCAN_NB];

// ================= CSR build =================
__global__ void k_zero_cnt() {
    int i = blockIdx.x * blockDim.x + threadIdx.x;
    if (i < N_NODES) g_cnt[i] = 0;
}

// edge_index is int32 on device: layout [2, E] row-major.
__global__ void k_count(const int* __restrict__ ei, int E) {
    int e = blockIdx.x * blockDim.x + threadIdx.x;
    if (e < E) atomicAdd(&g_cnt[ei[E + e]], 1);
}

__global__ void k_scan1() {
    __shared__ int sh[SCAN_BS];
    int i = blockIdx.x * SCAN_BS + threadIdx.x;
    int v = (i < N_NODES) ? g_cnt[i] : 0;
    sh[threadIdx.x] = v;
    __syncthreads();
    for (int off = 1; off < SCAN_BS; off <<= 1) {
        int t = (threadIdx.x >= off) ? sh[threadIdx.x - off] : 0;
        __syncthreads();
        sh[threadIdx.x] += t;
        __syncthreads();
    }
    if (i < N_NODES) g_scan[i] = sh[threadIdx.x];
    if (threadIdx.x == SCAN_BS - 1) g_bsum[blockIdx.x] = sh[threadIdx.x];
}

// merged: exclusive prefix of block sums computed locally, then finalize
__global__ void k_scan23() {
    __shared__ int pre[SCAN_NB];
    if (threadIdx.x < SCAN_NB) pre[threadIdx.x] = g_bsum[threadIdx.x];
    __syncthreads();
    if (threadIdx.x == 0) {
        int run = 0;
        #pragma unroll 1
        for (int b = 0; b < SCAN_NB; b++) { int v = pre[b]; pre[b] = run; run += v; }
    }
    __syncthreads();
    int i = blockIdx.x * blockDim.x + threadIdx.x;
    if (i < N_NODES) {
        int incl = g_scan[i] + pre[i / SCAN_BS];
        int cnt  = g_cnt[i];
        int excl = incl - cnt;
        g_rowptr[i] = excl;
        g_cursor[i] = excl;
        g_inv[i]    = 1.0f / fmaxf((float)cnt, 1.0f);
        if (i == N_NODES - 1) g_rowptr[N_NODES] = incl;
    }
}

__global__ void k_fill(const int* __restrict__ ei, int E) {
    int e = blockIdx.x * blockDim.x + threadIdx.x;
    if (e < E) {
        int src = ei[e];
        int dst = ei[E + e];
        int pos = atomicAdd(&g_cursor[dst], 1);
        g_eidx[pos] = src;
    }
}

// ================= gather-mean (no atomics, fp32 — known good) =================
__global__ __launch_bounds__(256)
void k_gather(const float* __restrict__ xext, int layer) {
    const float* feat = (layer == 0) ? xext : g_h1;
    int lane = threadIdx.x & 31;
    int node = blockIdx.x * 8 + (threadIdx.x >> 5);
    if (node >= N_NODES) return;

    int b = g_rowptr[node];
    int e = g_rowptr[node + 1];
    float4 acc = make_float4(0.f, 0.f, 0.f, 0.f);

    int j = b;
    for (; j + 4 <= e; j += 4) {
        int s0 = g_eidx[j + 0], s1 = g_eidx[j + 1];
        int s2 = g_eidx[j + 2], s3 = g_eidx[j + 3];
        float4 v0 = __ldg((const float4*)(feat + (size_t)s0 * D) + lane);
        float4 v1 = __ldg((const float4*)(feat + (size_t)s1 * D) + lane);
        float4 v2 = __ldg((const float4*)(feat + (size_t)s2 * D) + lane);
        float4 v3 = __ldg((const float4*)(feat + (size_t)s3 * D) + lane);
        acc.x += (v0.x + v1.x) + (v2.x + v3.x);
        acc.y += (v0.y + v1.y) + (v2.y + v3.y);
        acc.z += (v0.z + v1.z) + (v2.z + v3.z);
        acc.w += (v0.w + v1.w) + (v2.w + v3.w);
    }
    for (; j < e; j++) {
        int s = g_eidx[j];
        float4 v = __ldg((const float4*)(feat + (size_t)s * D) + lane);
        acc.x += v.x; acc.y += v.y; acc.z += v.z; acc.w += v.w;
    }
    float sc = g_inv[node];
    acc.x *= sc; acc.y *= sc; acc.z *= sc; acc.w *= sc;
    ((float4*)(g_agg + (size_t)node * D))[lane] = acc;
}

// ---- fast packed bf16 hi/lo split of a float4, 8B smem stores ----
__device__ __forceinline__ void split4_store(__nv_bfloat16* hi_base,
                                             __nv_bfloat16* lo_base,
                                             int off, float4 v) {
    uint32_t h01, h23, l01, l23;
    asm("cvt.rn.bf16x2.f32 %0, %1, %2;" : "=r"(h01) : "f"(v.y), "f"(v.x));
    asm("cvt.rn.bf16x2.f32 %0, %1, %2;" : "=r"(h23) : "f"(v.w), "f"(v.z));
    float hx = __uint_as_float(h01 << 16);
    float hy = __uint_as_float(h01 & 0xffff0000u);
    float hz = __uint_as_float(h23 << 16);
    float hw = __uint_as_float(h23 & 0xffff0000u);
    asm("cvt.rn.bf16x2.f32 %0, %1, %2;" : "=r"(l01) : "f"(v.y - hy), "f"(v.x - hx));
    asm("cvt.rn.bf16x2.f32 %0, %1, %2;" : "=r"(l23) : "f"(v.w - hw), "f"(v.z - hz));
    *(uint2*)(hi_base + off) = make_uint2(h01, h23);
    *(uint2*)(lo_base + off) = make_uint2(l01, l23);
}

#define MMA_BF16(C, A0, A1, A2, A3, B0, B1)                                    \
    asm volatile(                                                              \
        "mma.sync.aligned.m16n8k16.row.col.f32.bf16.bf16.f32 "                 \
        "{%0,%1,%2,%3}, {%4,%5,%6,%7}, {%8,%9}, {%0,%1,%2,%3};"                \
        : "+f"((C)[0]), "+f"((C)[1]), "+f"((C)[2]), "+f"((C)[3])               \
        : "r"(A0), "r"(A1), "r"(A2), "r"(A3), "r"(B0), "r"(B1))

// ================= fused SAGE layer — N-split across CTA pairs ===============
// grid = 296: even CTAs compute cols [0,64), odd CTAs cols [64,128).
// smem/CTA ~101KB -> 2 CTAs resident per SM (16 warps) for latency hiding.
// out = relu( [agg|xroot](50000x256) @ [wl;wr]^T + bl )
__global__ __launch_bounds__(256, 2)
void k_sage_mma(const float* __restrict__ xext,
                const float* __restrict__ wl, const float* __restrict__ bl,
                const float* __restrict__ wr, int layer, int tlimit) {
    extern __shared__ __nv_bfloat16 sm[];
    __nv_bfloat16* sB_hi = sm;                       // 64 * P2
    __nv_bfloat16* sB_lo = sB_hi + 64 * P2;
    __nv_bfloat16* sA_hi = sB_lo + 64 * P2;          // 32 * P2
    __nv_bfloat16* sA_lo = sA_hi + 32 * P2;

    const float* xroot = (layer == 0) ? xext : g_h1;
    float* out = (layer == 0) ? g_h1 : g_h2;

    const int tid  = threadIdx.x;
    const int lane = tid & 31;
    const int w    = tid >> 5;
    const int g    = lane >> 2;
    const int q    = lane & 3;
    const int mr   = (w & 1) * 16;        // warp row offset within 32-row tile
    const int n0l  = (w >> 1) * 16;       // warp col offset within this half (2 n8-tiles)
    const int half   = blockIdx.x & 1;
    const int n_base = half * 64;         // this CTA's output column base
    const int cstride = gridDim.x >> 1;   // tile stride (148)

    // stage this half's weights (hi/lo split): B rows [n_base, n_base+64), K=256
    for (int idx = tid; idx < 64 * 64; idx += 256) {
        int n  = idx >> 6;                 // local n 0..63
        int k4 = (idx & 63) * 4;
        int gn = n_base + n;
        float4 v = (k4 < 128) ? *(const float4*)&wl[gn * 128 + k4]
                              : *(const float4*)&wr[gn * 128 + (k4 - 128)];
        split4_store(sB_hi, sB_lo, n * P2 + k4, v);
    }
    float2 bias_t[2];
    #pragma unroll
    for (int t = 0; t < 2; t++)
        bias_t[t] = *(const float2*)&bl[n_base + n0l + t * 8 + q * 2];
    __syncthreads();

    for (int tile = blockIdx.x >> 1; tile < tlimit; tile += cstride) {
        const int row0 = tile * TM;
        __syncthreads();
        // stage A tile (32 x 256): [agg | xroot], hi/lo split, float4 path
        #pragma unroll 2
        for (int idx = tid; idx < TM * 64; idx += 256) {
            int r  = idx >> 6;
            int k4 = (idx & 63) * 4;
            int grow = row0 + r;
            float4 v = make_float4(0.f, 0.f, 0.f, 0.f);
            if (grow < N_NODES)
                v = (k4 < 128)
                    ? *(const float4*)&g_agg[(size_t)grow * D + k4]
                    : __ldg((const float4*)&xroot[(size_t)grow * D + (k4 - 128)]);
            split4_store(sA_hi, sA_lo, r * P2 + k4, v);
        }
        __syncthreads();

        float acc[2][4];
        #pragma unroll
        for (int t = 0; t < 2; t++)
            #pragma unroll
            for (int c = 0; c < 4; c++) acc[t][c] = 0.f;

        #pragma unroll 4
        for (int ks = 0; ks < 16; ks++) {
            const int kk = ks * 16 + q * 2;
            const int ra = (mr + g) * P2;
            uint32_t ah0 = *(const uint32_t*)&sA_hi[ra + kk];
            uint32_t ah1 = *(const uint32_t*)&sA_hi[ra + 8 * P2 + kk];
            uint32_t ah2 = *(const uint32_t*)&sA_hi[ra + kk + 8];
            uint32_t ah3 = *(const uint32_t*)&sA_hi[ra + 8 * P2 + kk + 8];
            uint32_t al0 = *(const uint32_t*)&sA_lo[ra + kk];
            uint32_t al1 = *(const uint32_t*)&sA_lo[ra + 8 * P2 + kk];
            uint32_t al2 = *(const uint32_t*)&sA_lo[ra + kk + 8];
            uint32_t al3 = *(const uint32_t*)&sA_lo[ra + 8 * P2 + kk + 8];
            #pragma unroll
            for (int t = 0; t < 2; t++) {
                const int nb = (n0l + t * 8 + g) * P2;
                uint32_t bh0 = *(const uint32_t*)&sB_hi[nb + kk];
                uint32_t bh1 = *(const uint32_t*)&sB_hi[nb + kk + 8];
                uint32_t bl0_ = *(const uint32_t*)&sB_lo[nb + kk];
                uint32_t bl1_ = *(const uint32_t*)&sB_lo[nb + kk + 8];
                MMA_BF16(acc[t], ah0, ah1, ah2, ah3, bh0, bh1);
                MMA_BF16(acc[t], ah0, ah1, ah2, ah3, bl0_, bl1_);
                MMA_BF16(acc[t], al0, al1, al2, al3, bh0, bh1);
            }
        }

        // epilogue: bias + relu, f32 store
        const int rA = row0 + mr + g;
        const int rB = rA + 8;
        #pragma unroll
        for (int t = 0; t < 2; t++) {
            const int col0 = n_base + n0l + t * 8 + q * 2;
            if (rA < N_NODES) {
                float2 o;
                o.x = fmaxf(acc[t][0] + bias_t[t].x, 0.f);
                o.y = fmaxf(acc[t][1] + bias_t[t].y, 0.f);
                *(float2*)&out[(size_t)rA * D + col0] = o;
            }
            if (rB < N_NODES) {
                float2 o;
                o.x = fmaxf(acc[t][2] + bias_t[t].x, 0.f);
                o.y = fmaxf(acc[t][3] + bias_t[t].y, 0.f);
                *(float2*)&out[(size_t)rB * D + col0] = o;
            }
        }
    }
}

// ================= fused MLP head (tensor core) =================
// h3 = relu(g_h2 @ mw1^T + mb1);  out = h3 @ mw2^T + mb2   -> [N]
__global__ __launch_bounds__(256, 2)
void k_mlp_mma(const float* __restrict__ mw1, const float* __restrict__ mb1,
               const float* __restrict__ mw2, const float* __restrict__ mb2,
               float* __restrict__ out) {
    extern __shared__ __nv_bfloat16 sm[];
    __nv_bfloat16* sB_hi = sm;                       // 128 * P1
    __nv_bfloat16* sB_lo = sB_hi + 128 * P1;
    __nv_bfloat16* sA_hi = sB_lo + 128 * P1;         // 32 * P1
    __nv_bfloat16* sA_lo = sA_hi + 32 * P1;
    float* s_part = (float*)(sA_lo + 32 * P1);       // [4][32]

    const int tid  = threadIdx.x;
    const int lane = tid & 31;
    const int w    = tid >> 5;
    const int g    = lane >> 2;
    const int q    = lane & 3;
    const int mr   = (w & 1) * 16;
    const int n0   = (w >> 1) * 32;
    const int grp  = w >> 1;

    for (int idx = tid; idx < 128 * 32; idx += 256) {
        int n  = idx >> 5;
        int k4 = (idx & 31) * 4;
        float4 v = *(const float4*)&mw1[n * 128 + k4];
        split4_store(sB_hi, sB_lo, n * P1 + k4, v);
    }
    float2 b1_t[4], w2_t[4];
    #pragma unroll
    for (int t = 0; t < 4; t++) {
        b1_t[t] = *(const float2*)&mb1[n0 + t * 8 + q * 2];
        w2_t[t] = *(const float2*)&mw2[n0 + t * 8 + q * 2];
    }
    const float b2 = mb2[0];
    __syncthreads();

    const int ntiles = NTILES;
    for (int tile = blockIdx.x; tile < ntiles; tile += gridDim.x) {
        const int row0 = tile * TM;
        __syncthreads();
        #pragma unroll 2
        for (int idx = tid; idx < TM * 32; idx += 256) {
            int r  = idx >> 5;
            int k4 = (idx & 31) * 4;
            int grow = row0 + r;
            float4 v = (grow < N_NODES)
                ? *(const float4*)&g_h2[(size_t)grow * D + k4]
                : make_float4(0.f, 0.f, 0.f, 0.f);
            split4_store(sA_hi, sA_lo, r * P1 + k4, v);
        }
        __syncthreads();

        float acc[4][4];
        #pragma unroll
        for (int t = 0; t < 4; t++)
            #pragma unroll
            for (int c = 0; c < 4; c++) acc[t][c] = 0.f;

        #pragma unroll 4
        for (int ks = 0; ks < 8; ks++) {
            const int kk = ks * 16 + q * 2;
            const int ra = (mr + g) * P1;
            uint32_t ah0 = *(const uint32_t*)&sA_hi[ra + kk];
            uint32_t ah1 = *(const uint32_t*)&sA_hi[ra + 8 * P1 + kk];
            uint32_t ah2 = *(const uint32_t*)&sA_hi[ra + kk + 8];
            uint32_t ah3 = *(const uint32_t*)&sA_hi[ra + 8 * P1 + kk + 8];
            uint32_t al0 = *(const uint32_t*)&sA_lo[ra + kk];
            uint32_t al1 = *(const uint32_t*)&sA_lo[ra + 8 * P1 + kk];
            uint32_t al2 = *(const uint32_t*)&sA_lo[ra + kk + 8];
            uint32_t al3 = *(const uint32_t*)&sA_lo[ra + 8 * P1 + kk + 8];
            #pragma unroll
            for (int t = 0; t < 4; t++) {
                const int nb = (n0 + t * 8 + g) * P1;
                uint32_t bh0 = *(const uint32_t*)&sB_hi[nb + kk];
                uint32_t bh1 = *(const uint32_t*)&sB_hi[nb + kk + 8];
                uint32_t bl0_ = *(const uint32_t*)&sB_lo[nb + kk];
                uint32_t bl1_ = *(const uint32_t*)&sB_lo[nb + kk + 8];
                MMA_BF16(acc[t], ah0, ah1, ah2, ah3, bh0, bh1);
                MMA_BF16(acc[t], ah0, ah1, ah2, ah3, bl0_, bl1_);
                MMA_BF16(acc[t], al0, al1, al2, al3, bh0, bh1);
            }
        }

        // head: relu then dot with mw2 over this warp's 32 cols
        float pg = 0.f, pg8 = 0.f;
        #pragma unroll
        for (int t = 0; t < 4; t++) {
            pg  += fmaxf(acc[t][0] + b1_t[t].x, 0.f) * w2_t[t].x
                 + fmaxf(acc[t][1] + b1_t[t].y, 0.f) * w2_t[t].y;
            pg8 += fmaxf(acc[t][2] + b1_t[t].x, 0.f) * w2_t[t].x
                 + fmaxf(acc[t][3] + b1_t[t].y, 0.f) * w2_t[t].y;
        }
        pg  += __shfl_xor_sync(0xffffffffu, pg, 1);
        pg  += __shfl_xor_sync(0xffffffffu, pg, 2);
        pg8 += __shfl_xor_sync(0xffffffffu, pg8, 1);
        pg8 += __shfl_xor_sync(0xffffffffu, pg8, 2);
        if (q == 0) {
            s_part[grp * 32 + mr + g]     = pg;
            s_part[grp * 32 + mr + g + 8] = pg8;
        }
        __syncthreads();
        if (tid < 32) {
            int grow = row0 + tid;
            if (grow < N_NODES) {
                out[grow] = s_part[tid] + s_part[32 + tid] + s_part[64 + tid]
                          + s_part[96 + tid] + b2;
            }
        }
    }
}

extern "C" void kernel_launch(void* const* d_in, const int* in_sizes, int n_in,
                              void* d_out, int out_size) {
    const float* x   = (const float*)d_in[0];
    const int*   ei  = (const int*)d_in[1];      // int32 (JAX x64 disabled)
    const float* w1l = (const float*)d_in[2];
    const float* b1l = (const float*)d_in[3];
    const float* w1r = (const float*)d_in[4];
    const float* w2l = (const float*)d_in[5];
    const float* b2l = (const float*)d_in[6];
    const float* w2r = (const float*)d_in[7];
    const float* mw1 = (const float*)d_in[8];
    const float* mb1 = (const float*)d_in[9];
    const float* mw2 = (const float*)d_in[10];
    const float* mb2 = (const float*)d_in[11];
    float* out = (float*)d_out;
    const int E = in_sizes[1] / 2;

    const int sage_smem = (2 * 64 * P2 + 2 * 32 * P2) * (int)sizeof(__nv_bfloat16); // 101376
    const int mlp_smem  = (2 * 128 * P1 + 2 * 32 * P1) * (int)sizeof(__nv_bfloat16)
                        + 4 * 32 * (int)sizeof(float);                               // 87552
    cudaFuncSetAttribute(k_sage_mma, cudaFuncAttributeMaxDynamicSharedMemorySize, sage_smem);
    cudaFuncSetAttribute(k_mlp_mma,  cudaFuncAttributeMaxDynamicSharedMemorySize, mlp_smem);

    // ---- CSR build ----
    k_zero_cnt<<<(N_NODES + 255) / 256, 256>>>();              // launch 1
    k_count<<<(E + 255) / 256, 256>>>(ei, E);                  // launch 2
    k_scan1<<<SCAN_NB, SCAN_BS>>>();                           // launch 3

    // launch 4 — PROFILING DUMMY (cheap: 1 tile/CTA via tlimit=148). Reads stale
    // g_agg (deterministic across replays); its partial g_h1 output is fully
    // overwritten by the real layer-1 sage below.
    k_sage_mma<<<296, 256, sage_smem>>>(x, w1l, b1l, w1r, 0, 148);

    k_scan23<<<(N_NODES + 255) / 256, 256>>>();                // launch 5
    k_fill<<<(E + 255) / 256, 256>>>(ei, E);                   // launch 6

    const int gat_blocks = (N_NODES + 7) / 8;

    // ---- layer 1 ----
    k_gather<<<gat_blocks, 256>>>(x, 0);
    k_sage_mma<<<296, 256, sage_smem>>>(x, w1l, b1l, w1r, 0, NTILES);

    // ---- layer 2 ----
    k_gather<<<gat_blocks, 256>>>(x, 1);
    k_sage_mma<<<296, 256, sage_smem>>>(x, w2l, b2l, w2r, 1, NTILES);

    // ---- MLP head ----
    k_mlp_mma<<<296, 256, mlp_smem>>>(mw1, mb1, mw2, mb2, out);
}

// round 13
// speedup vs baseline: 1.2455x; 1.0363x over previous
#include <cuda_runtime.h>
#include <cuda_bf16.h>
#include <cstdint>

#define N_NODES 50000
#define D 128
#define TM 32
#define NTILES ((N_NODES + TM - 1) / TM)   // 1563
#define SCAN_BS 1024
#define SCAN_NB ((N_NODES + SCAN_BS - 1) / SCAN_BS)   // 49
#define P2 264   // padded row stride (bf16 elems) for K=256 tiles
#define P1 136   // padded row stride for K=128 tiles

// ---- scratch (allocation-free: __device__ globals) ----
__device__ float g_agg[(size_t)N_NODES * D];
__device__ float g_h1 [(size_t)N_NODES * D];
__device__ float g_h2 [(size_t)N_NODES * D];
__device__ float g_inv[N_NODES];
__device__ int   g_cnt[N_NODES];
__device__ int   g_scan[N_NODES];
__device__ int   g_rowptr[N_NODES + 1];
__device__ int   g_cursor[N_NODES];
__device__ int   g_eidx[1700000];
__device__ int   g_bsum[SCAN_NB];

// ================= CSR build =================
__global__ void k_zero_cnt() {
    int i = blockIdx.x * blockDim.x + threadIdx.x;
    if (i < N_NODES) g_cnt[i] = 0;
}

__global__ void k_count(const int* __restrict__ ei, int E) {
    int e = blockIdx.x * blockDim.x + threadIdx.x;
    if (e < E) atomicAdd(&g_cnt[ei[E + e]], 1);
}

__global__ void k_scan1() {
    __shared__ int sh[SCAN_BS];
    int i = blockIdx.x * SCAN_BS + threadIdx.x;
    int v = (i < N_NODES) ? g_cnt[i] : 0;
    sh[threadIdx.x] = v;
    __syncthreads();
    for (int off = 1; off < SCAN_BS; off <<= 1) {
        int t = (threadIdx.x >= off) ? sh[threadIdx.x - off] : 0;
        __syncthreads();
        sh[threadIdx.x] += t;
        __syncthreads();
    }
    if (i < N_NODES) g_scan[i] = sh[threadIdx.x];
    if (threadIdx.x == SCAN_BS - 1) g_bsum[blockIdx.x] = sh[threadIdx.x];
}

__global__ void k_scan23() {
    __shared__ int pre[SCAN_NB];
    if (threadIdx.x < SCAN_NB) pre[threadIdx.x] = g_bsum[threadIdx.x];
    __syncthreads();
    if (threadIdx.x == 0) {
        int run = 0;
        #pragma unroll 1
        for (int b = 0; b < SCAN_NB; b++) { int v = pre[b]; pre[b] = run; run += v; }
    }
    __syncthreads();
    int i = blockIdx.x * blockDim.x + threadIdx.x;
    if (i < N_NODES) {
        int incl = g_scan[i] + pre[i / SCAN_BS];
        int cnt  = g_cnt[i];
        int excl = incl - cnt;
        g_rowptr[i] = excl;
        g_cursor[i] = excl;
        g_inv[i]    = 1.0f / fmaxf((float)cnt, 1.0f);
        if (i == N_NODES - 1) g_rowptr[N_NODES] = incl;
    }
}

__global__ void k_fill(const int* __restrict__ ei, int E) {
    int e = blockIdx.x * blockDim.x + threadIdx.x;
    if (e < E) {
        int src = ei[e];
        int dst = ei[E + e];
        int pos = atomicAdd(&g_cursor[dst], 1);
        g_eidx[pos] = src;
    }
}

// ================= gather-mean (no atomics, fp32 — known good) =================
__global__ __launch_bounds__(256)
void k_gather(const float* __restrict__ xext, int layer) {
    const float* feat = (layer == 0) ? xext : g_h1;
    int lane = threadIdx.x & 31;
    int node = blockIdx.x * 8 + (threadIdx.x >> 5);
    if (node >= N_NODES) return;

    int b = g_rowptr[node];
    int e = g_rowptr[node + 1];
    float4 acc = make_float4(0.f, 0.f, 0.f, 0.f);

    int j = b;
    for (; j + 4 <= e; j += 4) {
        int s0 = g_eidx[j + 0], s1 = g_eidx[j + 1];
        int s2 = g_eidx[j + 2], s3 = g_eidx[j + 3];
        float4 v0 = __ldg((const float4*)(feat + (size_t)s0 * D) + lane);
        float4 v1 = __ldg((const float4*)(feat + (size_t)s1 * D) + lane);
        float4 v2 = __ldg((const float4*)(feat + (size_t)s2 * D) + lane);
        float4 v3 = __ldg((const float4*)(feat + (size_t)s3 * D) + lane);
        acc.x += (v0.x + v1.x) + (v2.x + v3.x);
        acc.y += (v0.y + v1.y) + (v2.y + v3.y);
        acc.z += (v0.z + v1.z) + (v2.z + v3.z);
        acc.w += (v0.w + v1.w) + (v2.w + v3.w);
    }
    for (; j < e; j++) {
        int s = g_eidx[j];
        float4 v = __ldg((const float4*)(feat + (size_t)s * D) + lane);
        acc.x += v.x; acc.y += v.y; acc.z += v.z; acc.w += v.w;
    }
    float sc = g_inv[node];
    acc.x *= sc; acc.y *= sc; acc.z *= sc; acc.w *= sc;
    ((float4*)(g_agg + (size_t)node * D))[lane] = acc;
}

// ---- fast packed bf16 hi/lo split of a float4, 8B smem stores ----
__device__ __forceinline__ void split4_store(__nv_bfloat16* hi_base,
                                             __nv_bfloat16* lo_base,
                                             int off, float4 v) {
    uint32_t h01, h23, l01, l23;
    asm("cvt.rn.bf16x2.f32 %0, %1, %2;" : "=r"(h01) : "f"(v.y), "f"(v.x));
    asm("cvt.rn.bf16x2.f32 %0, %1, %2;" : "=r"(h23) : "f"(v.w), "f"(v.z));
    float hx = __uint_as_float(h01 << 16);
    float hy = __uint_as_float(h01 & 0xffff0000u);
    float hz = __uint_as_float(h23 << 16);
    float hw = __uint_as_float(h23 & 0xffff0000u);
    asm("cvt.rn.bf16x2.f32 %0, %1, %2;" : "=r"(l01) : "f"(v.y - hy), "f"(v.x - hx));
    asm("cvt.rn.bf16x2.f32 %0, %1, %2;" : "=r"(l23) : "f"(v.w - hw), "f"(v.z - hz));
    *(uint2*)(hi_base + off) = make_uint2(h01, h23);
    *(uint2*)(lo_base + off) = make_uint2(l01, l23);
}

#define MMA_BF16(C, A0, A1, A2, A3, B0, B1)                                    \
    asm volatile(                                                              \
        "mma.sync.aligned.m16n8k16.row.col.f32.bf16.bf16.f32 "                 \
        "{%0,%1,%2,%3}, {%4,%5,%6,%7}, {%8,%9}, {%0,%1,%2,%3};"                \
        : "+f"((C)[0]), "+f"((C)[1]), "+f"((C)[2]), "+f"((C)[3])               \
        : "r"(A0), "r"(A1), "r"(A2), "r"(A3), "r"(B0), "r"(B1))

#define LDSM_X4(R0, R1, R2, R3, ADDR)                                          \
    asm volatile("ldmatrix.sync.aligned.m8n8.x4.shared.b16 {%0,%1,%2,%3}, [%4];" \
        : "=r"(R0), "=r"(R1), "=r"(R2), "=r"(R3) : "r"(ADDR))

// ================= fused SAGE layer — N-split, ldmatrix operand fetch ========
// grid = 296: even CTAs cols [0,64), odd CTAs cols [64,128). 2 CTAs/SM.
__global__ __launch_bounds__(256, 2)
void k_sage_mma(const float* __restrict__ xext,
                const float* __restrict__ wl, const float* __restrict__ bl,
                const float* __restrict__ wr, int layer) {
    extern __shared__ __nv_bfloat16 sm[];
    __nv_bfloat16* sB_hi = sm;                       // 64 * P2
    __nv_bfloat16* sB_lo = sB_hi + 64 * P2;
    __nv_bfloat16* sA_hi = sB_lo + 64 * P2;          // 32 * P2
    __nv_bfloat16* sA_lo = sA_hi + 32 * P2;

    const float* xroot = (layer == 0) ? xext : g_h1;
    float* out = (layer == 0) ? g_h1 : g_h2;

    const int tid  = threadIdx.x;
    const int lane = tid & 31;
    const int w    = tid >> 5;
    const int g    = lane >> 2;
    const int q    = lane & 3;
    const int mr   = (w & 1) * 16;        // warp row offset in 32-row tile
    const int n0l  = (w >> 1) * 16;       // warp col offset within half (2 n8-tiles)
    const int half   = blockIdx.x & 1;
    const int n_base = half * 64;
    const int cstride = gridDim.x >> 1;   // 148

    // stage this half's weights: B rows [n_base, n_base+64), K=256 = [wl|wr]
    for (int idx = tid; idx < 64 * 64; idx += 256) {
        int n  = idx >> 6;
        int k4 = (idx & 63) * 4;
        int gn = n_base + n;
        float4 v = (k4 < 128) ? *(const float4*)&wl[gn * 128 + k4]
                              : *(const float4*)&wr[gn * 128 + (k4 - 128)];
        split4_store(sB_hi, sB_lo, n * P2 + k4, v);
    }
    float2 bias_t[2];
    #pragma unroll
    for (int t = 0; t < 2; t++)
        bias_t[t] = *(const float2*)&bl[n_base + n0l + t * 8 + q * 2];

    // ldmatrix lane addressing (per-warp, fixed rows; col advances with ks)
    const int lrow = lane & 7;
    const int lsel = (lane >> 3) & 1;
    const int lhi  = lane >> 4;
    // A x4: m0=(mr+r,k0..7) m1=(mr+8+r,k0..7) m2=(mr+r,k8..15) m3=(mr+8+r,k8..15)
    uint32_t a_row = (uint32_t)((mr + lrow + lsel * 8) * P2 + lhi * 8) * 2;
    // B x4: m0=(n+r,k0..7) m1=(n+r,k8..15) m2=(n+8+r,k0..7) m3=(n+8+r,k8..15)
    uint32_t b_row = (uint32_t)((n0l + lrow + lhi * 8) * P2 + lsel * 8) * 2;
    uint32_t sAhi_u = (uint32_t)__cvta_generic_to_shared(sA_hi) + a_row;
    uint32_t sAlo_u = (uint32_t)__cvta_generic_to_shared(sA_lo) + a_row;
    uint32_t sBhi_u = (uint32_t)__cvta_generic_to_shared(sB_hi) + b_row;
    uint32_t sBlo_u = (uint32_t)__cvta_generic_to_shared(sB_lo) + b_row;
    __syncthreads();

    for (int tile = blockIdx.x >> 1; tile < NTILES; tile += cstride) {
        const int row0 = tile * TM;
        __syncthreads();
        #pragma unroll 2
        for (int idx = tid; idx < TM * 64; idx += 256) {
            int r  = idx >> 6;
            int k4 = (idx & 63) * 4;
            int grow = row0 + r;
            float4 v = make_float4(0.f, 0.f, 0.f, 0.f);
            if (grow < N_NODES)
                v = (k4 < 128)
                    ? *(const float4*)&g_agg[(size_t)grow * D + k4]
                    : __ldg((const float4*)&xroot[(size_t)grow * D + (k4 - 128)]);
            split4_store(sA_hi, sA_lo, r * P2 + k4, v);
        }
        __syncthreads();

        float acc[2][4];
        #pragma unroll
        for (int t = 0; t < 2; t++)
            #pragma unroll
            for (int c = 0; c < 4; c++) acc[t][c] = 0.f;

        #pragma unroll 4
        for (int ks = 0; ks < 16; ks++) {
            const uint32_t cofs = (uint32_t)(ks * 32);   // 16 elems * 2B
            uint32_t ah0, ah1, ah2, ah3, al0, al1, al2, al3;
            uint32_t bh[4], blo[4];
            LDSM_X4(ah0, ah1, ah2, ah3, sAhi_u + cofs);
            LDSM_X4(al0, al1, al2, al3, sAlo_u + cofs);
            LDSM_X4(bh[0], bh[1], bh[2], bh[3], sBhi_u + cofs);
            LDSM_X4(blo[0], blo[1], blo[2], blo[3], sBlo_u + cofs);
            #pragma unroll
            for (int t = 0; t < 2; t++) {
                MMA_BF16(acc[t], ah0, ah1, ah2, ah3, bh[2 * t], bh[2 * t + 1]);
                MMA_BF16(acc[t], ah0, ah1, ah2, ah3, blo[2 * t], blo[2 * t + 1]);
                MMA_BF16(acc[t], al0, al1, al2, al3, bh[2 * t], bh[2 * t + 1]);
            }
        }

        const int rA = row0 + mr + g;
        const int rB = rA + 8;
        #pragma unroll
        for (int t = 0; t < 2; t++) {
            const int col0 = n_base + n0l + t * 8 + q * 2;
            if (rA < N_NODES) {
                float2 o;
                o.x = fmaxf(acc[t][0] + bias_t[t].x, 0.f);
                o.y = fmaxf(acc[t][1] + bias_t[t].y, 0.f);
                *(float2*)&out[(size_t)rA * D + col0] = o;
            }
            if (rB < N_NODES) {
                float2 o;
                o.x = fmaxf(acc[t][2] + bias_t[t].x, 0.f);
                o.y = fmaxf(acc[t][3] + bias_t[t].y, 0.f);
                *(float2*)&out[(size_t)rB * D + col0] = o;
            }
        }
    }
}

// ================= fused MLP head (tensor core, ldmatrix) =================
__global__ __launch_bounds__(256, 2)
void k_mlp_mma(const float* __restrict__ mw1, const float* __restrict__ mb1,
               const float* __restrict__ mw2, const float* __restrict__ mb2,
               float* __restrict__ out) {
    extern __shared__ __nv_bfloat16 sm[];
    __nv_bfloat16* sB_hi = sm;                       // 128 * P1
    __nv_bfloat16* sB_lo = sB_hi + 128 * P1;
    __nv_bfloat16* sA_hi = sB_lo + 128 * P1;         // 32 * P1
    __nv_bfloat16* sA_lo = sA_hi + 32 * P1;
    float* s_part = (float*)(sA_lo + 32 * P1);       // [4][32]

    const int tid  = threadIdx.x;
    const int lane = tid & 31;
    const int w    = tid >> 5;
    const int g    = lane >> 2;
    const int q    = lane & 3;
    const int mr   = (w & 1) * 16;
    const int n0   = (w >> 1) * 32;
    const int grp  = w >> 1;

    for (int idx = tid; idx < 128 * 32; idx += 256) {
        int n  = idx >> 5;
        int k4 = (idx & 31) * 4;
        float4 v = *(const float4*)&mw1[n * 128 + k4];
        split4_store(sB_hi, sB_lo, n * P1 + k4, v);
    }
    float2 b1_t[4], w2_t[4];
    #pragma unroll
    for (int t = 0; t < 4; t++) {
        b1_t[t] = *(const float2*)&mb1[n0 + t * 8 + q * 2];
        w2_t[t] = *(const float2*)&mw2[n0 + t * 8 + q * 2];
    }
    const float b2 = mb2[0];

    const int lrow = lane & 7;
    const int lsel = (lane >> 3) & 1;
    const int lhi  = lane >> 4;
    uint32_t a_row = (uint32_t)((mr + lrow + lsel * 8) * P1 + lhi * 8) * 2;
    uint32_t b_row0 = (uint32_t)((n0 + lrow + lhi * 8) * P1 + lsel * 8) * 2;        // t0,t1
    uint32_t b_row1 = (uint32_t)((n0 + 16 + lrow + lhi * 8) * P1 + lsel * 8) * 2;   // t2,t3
    uint32_t sAhi_u = (uint32_t)__cvta_generic_to_shared(sA_hi) + a_row;
    uint32_t sAlo_u = (uint32_t)__cvta_generic_to_shared(sA_lo) + a_row;
    uint32_t sBhi0_u = (uint32_t)__cvta_generic_to_shared(sB_hi) + b_row0;
    uint32_t sBhi1_u = (uint32_t)__cvta_generic_to_shared(sB_hi) + b_row1;
    uint32_t sBlo0_u = (uint32_t)__cvta_generic_to_shared(sB_lo) + b_row0;
    uint32_t sBlo1_u = (uint32_t)__cvta_generic_to_shared(sB_lo) + b_row1;
    __syncthreads();

    for (int tile = blockIdx.x; tile < NTILES; tile += gridDim.x) {
        const int row0 = tile * TM;
        __syncthreads();
        #pragma unroll 2
        for (int idx = tid; idx < TM * 32; idx += 256) {
            int r  = idx >> 5;
            int k4 = (idx & 31) * 4;
            int grow = row0 + r;
            float4 v = (grow < N_NODES)
                ? *(const float4*)&g_h2[(size_t)grow * D + k4]
                : make_float4(0.f, 0.f, 0.f, 0.f);
            split4_store(sA_hi, sA_lo, r * P1 + k4, v);
        }
        __syncthreads();

        float acc[4][4];
        #pragma unroll
        for (int t = 0; t < 4; t++)
            #pragma unroll
            for (int c = 0; c < 4; c++) acc[t][c] = 0.f;

        #pragma unroll 2
        for (int ks = 0; ks < 8; ks++) {
            const uint32_t cofs = (uint32_t)(ks * 32);
            uint32_t ah0, ah1, ah2, ah3, al0, al1, al2, al3;
            uint32_t bh[8], blo[8];
            LDSM_X4(ah0, ah1, ah2, ah3, sAhi_u + cofs);
            LDSM_X4(al0, al1, al2, al3, sAlo_u + cofs);
            LDSM_X4(bh[0], bh[1], bh[2], bh[3], sBhi0_u + cofs);
            LDSM_X4(bh[4], bh[5], bh[6], bh[7], sBhi1_u + cofs);
            LDSM_X4(blo[0], blo[1], blo[2], blo[3], sBlo0_u + cofs);
            LDSM_X4(blo[4], blo[5], blo[6], blo[7], sBlo1_u + cofs);
            #pragma unroll
            for (int t = 0; t < 4; t++) {
                MMA_BF16(acc[t], ah0, ah1, ah2, ah3, bh[2 * t], bh[2 * t + 1]);
                MMA_BF16(acc[t], ah0, ah1, ah2, ah3, blo[2 * t], blo[2 * t + 1]);
                MMA_BF16(acc[t], al0, al1, al2, al3, bh[2 * t], bh[2 * t + 1]);
            }
        }

        float pg = 0.f, pg8 = 0.f;
        #pragma unroll
        for (int t = 0; t < 4; t++) {
            pg  += fmaxf(acc[t][0] + b1_t[t].x, 0.f) * w2_t[t].x
                 + fmaxf(acc[t][1] + b1_t[t].y, 0.f) * w2_t[t].y;
            pg8 += fmaxf(acc[t][2] + b1_t[t].x, 0.f) * w2_t[t].x
                 + fmaxf(acc[t][3] + b1_t[t].y, 0.f) * w2_t[t].y;
        }
        pg  += __shfl_xor_sync(0xffffffffu, pg, 1);
        pg  += __shfl_xor_sync(0xffffffffu, pg, 2);
        pg8 += __shfl_xor_sync(0xffffffffu, pg8, 1);
        pg8 += __shfl_xor_sync(0xffffffffu, pg8, 2);
        if (q == 0) {
            s_part[grp * 32 + mr + g]     = pg;
            s_part[grp * 32 + mr + g + 8] = pg8;
        }
        __syncthreads();
        if (tid < 32) {
            int grow = row0 + tid;
            if (grow < N_NODES) {
                out[grow] = s_part[tid] + s_part[32 + tid] + s_part[64 + tid]
                          + s_part[96 + tid] + b2;
            }
        }
    }
}

extern "C" void kernel_launch(void* const* d_in, const int* in_sizes, int n_in,
                              void* d_out, int out_size) {
    const float* x   = (const float*)d_in[0];
    const int*   ei  = (const int*)d_in[1];      // int32 (JAX x64 disabled)
    const float* w1l = (const float*)d_in[2];
    const float* b1l = (const float*)d_in[3];
    const float* w1r = (const float*)d_in[4];
    const float* w2l = (const float*)d_in[5];
    const float* b2l = (const float*)d_in[6];
    const float* w2r = (const float*)d_in[7];
    const float* mw1 = (const float*)d_in[8];
    const float* mb1 = (const float*)d_in[9];
    const float* mw2 = (const float*)d_in[10];
    const float* mb2 = (const float*)d_in[11];
    float* out = (float*)d_out;
    const int E = in_sizes[1] / 2;

    const int sage_smem = (2 * 64 * P2 + 2 * 32 * P2) * (int)sizeof(__nv_bfloat16); // 101376
    const int mlp_smem  = (2 * 128 * P1 + 2 * 32 * P1) * (int)sizeof(__nv_bfloat16)
                        + 4 * 32 * (int)sizeof(float);                               // 87552
    cudaFuncSetAttribute(k_sage_mma, cudaFuncAttributeMaxDynamicSharedMemorySize, sage_smem);
    cudaFuncSetAttribute(k_mlp_mma,  cudaFuncAttributeMaxDynamicSharedMemorySize, mlp_smem);

    // ---- CSR build ----
    k_zero_cnt<<<(N_NODES + 255) / 256, 256>>>();
    k_count<<<(E + 255) / 256, 256>>>(ei, E);
    k_scan1<<<SCAN_NB, SCAN_BS>>>();
    k_scan23<<<(N_NODES + 255) / 256, 256>>>();
    k_fill<<<(E + 255) / 256, 256>>>(ei, E);

    const int gat_blocks = (N_NODES + 7) / 8;

    // ---- layer 1 ----
    k_gather<<<gat_blocks, 256>>>(x, 0);
    k_sage_mma<<<296, 256, sage_smem>>>(x, w1l, b1l, w1r, 0);

    // ---- layer 2 ----
    k_gather<<<gat_blocks, 256>>>(x, 1);
    k_sage_mma<<<296, 256, sage_smem>>>(x, w2l, b2l, w2r, 1);

    // ---- MLP head ----
    k_mlp_mma<<<296, 256, mlp_smem>>>(mw1, mb1, mw2, mb2, out);
}

// round 15
// speedup vs baseline: 1.3207x; 1.0604x over previous
#include <cuda_runtime.h>
#include <cuda_fp16.h>
#include <cstdint>

#define N_NODES 50000
#define D 128
#define TM 32
#define NTILES ((N_NODES + TM - 1) / TM)           // 1563
#define SCAN_BS 1024
#define SCAN_NB ((N_NODES + SCAN_BS - 1) / SCAN_BS)   // 49
#define P2 264   // padded row stride (fp16 elems) for K=256 tiles
#define P1 136   // padded row stride for K=128 tiles

// ---- scratch (allocation-free: __device__ globals; zero-initialized) ----
__device__ float g_agg[(size_t)N_NODES * D];
__device__ float g_h1 [(size_t)N_NODES * D];
__device__ float g_h2 [(size_t)N_NODES * D];
__device__ float g_inv[N_NODES];
__device__ int   g_cnt[N_NODES];        // zero at entry; re-zeroed by k_fill
__device__ int   g_scan[N_NODES];
__device__ int   g_rowptr[N_NODES + 1];
__device__ int   g_cursor[N_NODES];
__device__ int   g_eidx[1700000];
__device__ int   g_bsum[SCAN_NB];

// ================= CSR build =================
__global__ void k_count(const int* __restrict__ ei, int E) {
    int e = blockIdx.x * blockDim.x + threadIdx.x;
    if (e < E) atomicAdd(&g_cnt[ei[E + e]], 1);
}

__global__ void k_scan1() {
    __shared__ int sh[SCAN_BS];
    int i = blockIdx.x * SCAN_BS + threadIdx.x;
    int v = (i < N_NODES) ? g_cnt[i] : 0;
    sh[threadIdx.x] = v;
    __syncthreads();
    for (int off = 1; off < SCAN_BS; off <<= 1) {
        int t = (threadIdx.x >= off) ? sh[threadIdx.x - off] : 0;
        __syncthreads();
        sh[threadIdx.x] += t;
        __syncthreads();
    }
    if (i < N_NODES) g_scan[i] = sh[threadIdx.x];
    if (threadIdx.x == SCAN_BS - 1) g_bsum[blockIdx.x] = sh[threadIdx.x];
}

__global__ void k_scan23() {
    __shared__ int pre[SCAN_NB];
    if (threadIdx.x < SCAN_NB) pre[threadIdx.x] = g_bsum[threadIdx.x];
    __syncthreads();
    if (threadIdx.x == 0) {
        int run = 0;
        #pragma unroll 1
        for (int b = 0; b < SCAN_NB; b++) { int v = pre[b]; pre[b] = run; run += v; }
    }
    __syncthreads();
    int i = blockIdx.x * blockDim.x + threadIdx.x;
    if (i < N_NODES) {
        int incl = g_scan[i] + pre[i / SCAN_BS];
        int cnt  = g_cnt[i];
        int excl = incl - cnt;
        g_rowptr[i] = excl;
        g_cursor[i] = excl;
        g_inv[i]    = 1.0f / fmaxf((float)cnt, 1.0f);
        if (i == N_NODES - 1) g_rowptr[N_NODES] = incl;
    }
}

// fill CSR; also re-zero g_cnt for the NEXT invocation (scan23 was its last reader)
__global__ void k_fill(const int* __restrict__ ei, int E) {
    int e = blockIdx.x * blockDim.x + threadIdx.x;
    if (e < N_NODES) g_cnt[e] = 0;
    if (e < E) {
        int src = ei[e];
        int dst = ei[E + e];
        int pos = atomicAdd(&g_cursor[dst], 1);
        g_eidx[pos] = src;
    }
}

// ================= gather-mean (no atomics, fp32 — known good) =================
__global__ __launch_bounds__(256)
void k_gather(const float* __restrict__ xext, int layer) {
    const float* feat = (layer == 0) ? xext : g_h1;
    int lane = threadIdx.x & 31;
    int node = blockIdx.x * 8 + (threadIdx.x >> 5);
    if (node >= N_NODES) return;

    int b = g_rowptr[node];
    int e = g_rowptr[node + 1];
    float4 acc = make_float4(0.f, 0.f, 0.f, 0.f);

    int j = b;
    for (; j + 4 <= e; j += 4) {
        int s0 = g_eidx[j + 0], s1 = g_eidx[j + 1];
        int s2 = g_eidx[j + 2], s3 = g_eidx[j + 3];
        float4 v0 = __ldg((const float4*)(feat + (size_t)s0 * D) + lane);
        float4 v1 = __ldg((const float4*)(feat + (size_t)s1 * D) + lane);
        float4 v2 = __ldg((const float4*)(feat + (size_t)s2 * D) + lane);
        float4 v3 = __ldg((const float4*)(feat + (size_t)s3 * D) + lane);
        acc.x += (v0.x + v1.x) + (v2.x + v3.x);
        acc.y += (v0.y + v1.y) + (v2.y + v3.y);
        acc.z += (v0.z + v1.z) + (v2.z + v3.z);
        acc.w += (v0.w + v1.w) + (v2.w + v3.w);
    }
    for (; j < e; j++) {
        int s = g_eidx[j];
        float4 v = __ldg((const float4*)(feat + (size_t)s * D) + lane);
        acc.x += v.x; acc.y += v.y; acc.z += v.z; acc.w += v.w;
    }
    float sc = g_inv[node];
    acc.x *= sc; acc.y *= sc; acc.z *= sc; acc.w *= sc;
    ((float4*)(g_agg + (size_t)node * D))[lane] = acc;
}

// ---- fp16 helpers ----
// A staging (hot): single fp16, packed 8B store.
__device__ __forceinline__ void pack4_f16_store(__half* base, int off, float4 v) {
    uint32_t p01, p23;
    asm("cvt.rn.f16x2.f32 %0, %1, %2;" : "=r"(p01) : "f"(v.y), "f"(v.x));
    asm("cvt.rn.f16x2.f32 %0, %1, %2;" : "=r"(p23) : "f"(v.w), "f"(v.z));
    *(uint2*)(base + off) = make_uint2(p01, p23);
}

// B staging (cold, once per launch): exact fp16 hi/lo split.
__device__ __forceinline__ void splitB_store(__half* hi, __half* lo, int off, float4 v) {
    float vv[4] = {v.x, v.y, v.z, v.w};
    #pragma unroll
    for (int i = 0; i < 4; i++) {
        __half h = __float2half_rn(vv[i]);
        hi[off + i] = h;
        lo[off + i] = __float2half_rn(vv[i] - __half2float(h));
    }
}

#define MMA_F16(C, A0, A1, A2, A3, B0, B1)                                     \
    asm volatile(                                                              \
        "mma.sync.aligned.m16n8k16.row.col.f32.f16.f16.f32 "                   \
        "{%0,%1,%2,%3}, {%4,%5,%6,%7}, {%8,%9}, {%0,%1,%2,%3};"                \
        : "+f"((C)[0]), "+f"((C)[1]), "+f"((C)[2]), "+f"((C)[3])               \
        : "r"(A0), "r"(A1), "r"(A2), "r"(A3), "r"(B0), "r"(B1))

// ================= fused SAGE layer (fp16 2-term: A single, B hi/lo) =========
// out = relu( [agg|xroot](50000x256) @ [wl;wr]^T + bl )
__global__ __launch_bounds__(256, 1)
void k_sage_mma(const float* __restrict__ xext,
                const float* __restrict__ wl, const float* __restrict__ bl,
                const float* __restrict__ wr, int layer) {
    extern __shared__ __half sm[];
    __half* sB_hi = sm;                      // 128 * P2
    __half* sB_lo = sB_hi + 128 * P2;        // 128 * P2
    __half* sA    = sB_lo + 128 * P2;        // 32 * P2

    const float* xroot = (layer == 0) ? xext : g_h1;
    float* out = (layer == 0) ? g_h1 : g_h2;

    const int tid  = threadIdx.x;
    const int lane = tid & 31;
    const int w    = tid >> 5;
    const int g    = lane >> 2;
    const int q    = lane & 3;
    const int mr   = (w & 1) * 16;     // warp row offset within 32-row tile
    const int n0   = (w >> 1) * 32;    // warp col offset (4 n8-tiles)

    // stage weights (fp16 hi/lo split): B[n][k], K=256 = [wl | wr]
    for (int idx = tid; idx < 128 * 64; idx += 256) {
        int n  = idx >> 6;
        int k4 = (idx & 63) * 4;
        float4 v = (k4 < 128) ? *(const float4*)&wl[n * 128 + k4]
                              : *(const float4*)&wr[n * 128 + (k4 - 128)];
        splitB_store(sB_hi, sB_lo, n * P2 + k4, v);
    }
    float2 bias_t[4];
    #pragma unroll
    for (int t = 0; t < 4; t++)
        bias_t[t] = *(const float2*)&bl[n0 + t * 8 + q * 2];
    __syncthreads();

    for (int tile = blockIdx.x; tile < NTILES; tile += gridDim.x) {
        const int row0 = tile * TM;
        __syncthreads();
        // stage A tile (32 x 256): [agg | xroot], single fp16
        #pragma unroll 2
        for (int idx = tid; idx < TM * 64; idx += 256) {
            int r  = idx >> 6;
            int k4 = (idx & 63) * 4;
            int grow = row0 + r;
            float4 v = make_float4(0.f, 0.f, 0.f, 0.f);
            if (grow < N_NODES)
                v = (k4 < 128)
                    ? *(const float4*)&g_agg[(size_t)grow * D + k4]
                    : __ldg((const float4*)&xroot[(size_t)grow * D + (k4 - 128)]);
            pack4_f16_store(sA, r * P2 + k4, v);
        }
        __syncthreads();

        float acc[4][4];
        #pragma unroll
        for (int t = 0; t < 4; t++)
            #pragma unroll
            for (int c = 0; c < 4; c++) acc[t][c] = 0.f;

        #pragma unroll 4
        for (int ks = 0; ks < 16; ks++) {
            const int kk = ks * 16 + q * 2;
            const int ra = (mr + g) * P2;
            uint32_t a0 = *(const uint32_t*)&sA[ra + kk];
            uint32_t a1 = *(const uint32_t*)&sA[ra + 8 * P2 + kk];
            uint32_t a2 = *(const uint32_t*)&sA[ra + kk + 8];
            uint32_t a3 = *(const uint32_t*)&sA[ra + 8 * P2 + kk + 8];
            #pragma unroll
            for (int t = 0; t < 4; t++) {
                const int nb = (n0 + t * 8 + g) * P2;
                uint32_t bh0 = *(const uint32_t*)&sB_hi[nb + kk];
                uint32_t bh1 = *(const uint32_t*)&sB_hi[nb + kk + 8];
                uint32_t bl0 = *(const uint32_t*)&sB_lo[nb + kk];
                uint32_t bl1 = *(const uint32_t*)&sB_lo[nb + kk + 8];
                MMA_F16(acc[t], a0, a1, a2, a3, bh0, bh1);
                MMA_F16(acc[t], a0, a1, a2, a3, bl0, bl1);
            }
        }

        // epilogue: bias + relu, f32 store
        const int rA = row0 + mr + g;
        const int rB = rA + 8;
        #pragma unroll
        for (int t = 0; t < 4; t++) {
            const int col0 = n0 + t * 8 + q * 2;
            if (rA < N_NODES) {
                float2 o;
                o.x = fmaxf(acc[t][0] + bias_t[t].x, 0.f);
                o.y = fmaxf(acc[t][1] + bias_t[t].y, 0.f);
                *(float2*)&out[(size_t)rA * D + col0] = o;
            }
            if (rB < N_NODES) {
                float2 o;
                o.x = fmaxf(acc[t][2] + bias_t[t].x, 0.f);
                o.y = fmaxf(acc[t][3] + bias_t[t].y, 0.f);
                *(float2*)&out[(size_t)rB * D + col0] = o;
            }
        }
    }
}

// ================= fused MLP head (fp16 2-term) =================
// h3 = relu(g_h2 @ mw1^T + mb1);  out = h3 @ mw2^T + mb2   -> [N]
__global__ __launch_bounds__(256, 2)
void k_mlp_mma(const float* __restrict__ mw1, const float* __restrict__ mb1,
               const float* __restrict__ mw2, const float* __restrict__ mb2,
               float* __restrict__ out) {
    extern __shared__ __half sm[];
    __half* sB_hi = sm;                      // 128 * P1
    __half* sB_lo = sB_hi + 128 * P1;
    __half* sA    = sB_lo + 128 * P1;        // 32 * P1
    float* s_part = (float*)(sA + 32 * P1);  // [4][32]

    const int tid  = threadIdx.x;
    const int lane = tid & 31;
    const int w    = tid >> 5;
    const int g    = lane >> 2;
    const int q    = lane & 3;
    const int mr   = (w & 1) * 16;
    const int n0   = (w >> 1) * 32;
    const int grp  = w >> 1;

    for (int idx = tid; idx < 128 * 32; idx += 256) {
        int n  = idx >> 5;
        int k4 = (idx & 31) * 4;
        float4 v = *(const float4*)&mw1[n * 128 + k4];
        splitB_store(sB_hi, sB_lo, n * P1 + k4, v);
    }
    float2 b1_t[4], w2_t[4];
    #pragma unroll
    for (int t = 0; t < 4; t++) {
        b1_t[t] = *(const float2*)&mb1[n0 + t * 8 + q * 2];
        w2_t[t] = *(const float2*)&mw2[n0 + t * 8 + q * 2];
    }
    const float b2 = mb2[0];
    __syncthreads();

    for (int tile = blockIdx.x; tile < NTILES; tile += gridDim.x) {
        const int row0 = tile * TM;
        __syncthreads();
        #pragma unroll 2
        for (int idx = tid; idx < TM * 32; idx += 256) {
            int r  = idx >> 5;
            int k4 = (idx & 31) * 4;
            int grow = row0 + r;
            float4 v = (grow < N_NODES)
                ? *(const float4*)&g_h2[(size_t)grow * D + k4]
                : make_float4(0.f, 0.f, 0.f, 0.f);
            pack4_f16_store(sA, r * P1 + k4, v);
        }
        __syncthreads();

        float acc[4][4];
        #pragma unroll
        for (int t = 0; t < 4; t++)
            #pragma unroll
            for (int c = 0; c < 4; c++) acc[t][c] = 0.f;

        #pragma unroll 4
        for (int ks = 0; ks < 8; ks++) {
            const int kk = ks * 16 + q * 2;
            const int ra = (mr + g) * P1;
            uint32_t a0 = *(const uint32_t*)&sA[ra + kk];
            uint32_t a1 = *(const uint32_t*)&sA[ra + 8 * P1 + kk];
            uint32_t a2 = *(const uint32_t*)&sA[ra + kk + 8];
            uint32_t a3 = *(const uint32_t*)&sA[ra + 8 * P1 + kk + 8];
            #pragma unroll
            for (int t = 0; t < 4; t++) {
                const int nb = (n0 + t * 8 + g) * P1;
                uint32_t bh0 = *(const uint32_t*)&sB_hi[nb + kk];
                uint32_t bh1 = *(const uint32_t*)&sB_hi[nb + kk + 8];
                uint32_t bl0 = *(const uint32_t*)&sB_lo[nb + kk];
                uint32_t bl1 = *(const uint32_t*)&sB_lo[nb + kk + 8];
                MMA_F16(acc[t], a0, a1, a2, a3, bh0, bh1);
                MMA_F16(acc[t], a0, a1, a2, a3, bl0, bl1);
            }
        }

        // head: relu then dot with mw2 over this warp's 32 cols
        float pg = 0.f, pg8 = 0.f;
        #pragma unroll
        for (int t = 0; t < 4; t++) {
            pg  += fmaxf(acc[t][0] + b1_t[t].x, 0.f) * w2_t[t].x
                 + fmaxf(acc[t][1] + b1_t[t].y, 0.f) * w2_t[t].y;
            pg8 += fmaxf(acc[t][2] + b1_t[t].x, 0.f) * w2_t[t].x
                 + fmaxf(acc[t][3] + b1_t[t].y, 0.f) * w2_t[t].y;
        }
        pg  += __shfl_xor_sync(0xffffffffu, pg, 1);
        pg  += __shfl_xor_sync(0xffffffffu, pg, 2);
        pg8 += __shfl_xor_sync(0xffffffffu, pg8, 1);
        pg8 += __shfl_xor_sync(0xffffffffu, pg8, 2);
        if (q == 0) {
            s_part[grp * 32 + mr + g]     = pg;
            s_part[grp * 32 + mr + g + 8] = pg8;
        }
        __syncthreads();
        if (tid < 32) {
            int grow = row0 + tid;
            if (grow < N_NODES) {
                out[grow] = s_part[tid] + s_part[32 + tid] + s_part[64 + tid]
                          + s_part[96 + tid] + b2;
            }
        }
    }
}

extern "C" void kernel_launch(void* const* d_in, const int* in_sizes, int n_in,
                              void* d_out, int out_size) {
    const float* x   = (const float*)d_in[0];
    const int*   ei  = (const int*)d_in[1];      // int32 (JAX x64 disabled)
    const float* w1l = (const float*)d_in[2];
    const float* b1l = (const float*)d_in[3];
    const float* w1r = (const float*)d_in[4];
    const float* w2l = (const float*)d_in[5];
    const float* b2l = (const float*)d_in[6];
    const float* w2r = (const float*)d_in[7];
    const float* mw1 = (const float*)d_in[8];
    const float* mb1 = (const float*)d_in[9];
    const float* mw2 = (const float*)d_in[10];
    const float* mb2 = (const float*)d_in[11];
    float* out = (float*)d_out;
    const int E = in_sizes[1] / 2;

    const int sage_smem = (2 * 128 * P2 + 32 * P2) * (int)sizeof(__half);  // 152064
    const int mlp_smem  = (2 * 128 * P1 + 32 * P1) * (int)sizeof(__half)
                        + 4 * 32 * (int)sizeof(float);                     // 78848
    cudaFuncSetAttribute(k_sage_mma, cudaFuncAttributeMaxDynamicSharedMemorySize, sage_smem);
    cudaFuncSetAttribute(k_mlp_mma,  cudaFuncAttributeMaxDynamicSharedMemorySize, mlp_smem);

    // ---- CSR build (g_cnt is zero at entry: zero-init + k_fill re-zero) ----
    k_count<<<(E + 255) / 256, 256>>>(ei, E);
    k_scan1<<<SCAN_NB, SCAN_BS>>>();
    k_scan23<<<(N_NODES + 255) / 256, 256>>>();
    k_fill<<<(E + 255) / 256, 256>>>(ei, E);

    const int gat_blocks = (N_NODES + 7) / 8;

    // ---- layer 1 ----
    k_gather<<<gat_blocks, 256>>>(x, 0);
    k_sage_mma<<<148, 256, sage_smem>>>(x, w1l, b1l, w1r, 0);

    // ---- layer 2 ----
    k_gather<<<gat_blocks, 256>>>(x, 1);
    k_sage_mma<<<148, 256, sage_smem>>>(x, w2l, b2l, w2r, 1);

    // ---- MLP head ----
    k_mlp_mma<<<296, 256, mlp_smem>>>(mw1, mb1, mw2, mb2, out);
}

// round 16
// speedup vs baseline: 1.5323x; 1.1602x over previous
#include <cuda_runtime.h>
#include <cuda_fp16.h>
#include <cstdint>

#define N_NODES 50000
#define D 128
#define TM 32
#define NTILES ((N_NODES + TM - 1) / TM)           // 1563
#define SCAN_BS 1024
#define SCAN_NB ((N_NODES + SCAN_BS - 1) / SCAN_BS)   // 49
#define P2 264   // padded row stride (fp16 elems) for K=256 tiles
#define P1 136   // padded row stride for K=128 tiles

// ---- scratch (allocation-free: __device__ globals; zero-initialized) ----
__device__ float g_agg[(size_t)N_NODES * D];
__device__ float g_h1 [(size_t)N_NODES * D];
__device__ float g_h2 [(size_t)N_NODES * D];
__device__ float g_inv[N_NODES];
__device__ int   g_cnt[N_NODES];        // zero at entry; re-zeroed by k_fill
__device__ int   g_scan[N_NODES];
__device__ int   g_rowptr[N_NODES + 1];
__device__ int   g_cursor[N_NODES];
__device__ int   g_eidx[1700000];
__device__ int   g_bsum[SCAN_NB];

// ================= CSR build =================
__global__ void k_count(const int* __restrict__ ei, int E) {
    int e = blockIdx.x * blockDim.x + threadIdx.x;
    if (e < E) atomicAdd(&g_cnt[ei[E + e]], 1);
}

__global__ void k_scan1() {
    __shared__ int sh[SCAN_BS];
    int i = blockIdx.x * SCAN_BS + threadIdx.x;
    int v = (i < N_NODES) ? g_cnt[i] : 0;
    sh[threadIdx.x] = v;
    __syncthreads();
    for (int off = 1; off < SCAN_BS; off <<= 1) {
        int t = (threadIdx.x >= off) ? sh[threadIdx.x - off] : 0;
        __syncthreads();
        sh[threadIdx.x] += t;
        __syncthreads();
    }
    if (i < N_NODES) g_scan[i] = sh[threadIdx.x];
    if (threadIdx.x == SCAN_BS - 1) g_bsum[blockIdx.x] = sh[threadIdx.x];
}

__global__ void k_scan23() {
    __shared__ int pre[SCAN_NB];
    if (threadIdx.x < SCAN_NB) pre[threadIdx.x] = g_bsum[threadIdx.x];
    __syncthreads();
    if (threadIdx.x == 0) {
        int run = 0;
        #pragma unroll 1
        for (int b = 0; b < SCAN_NB; b++) { int v = pre[b]; pre[b] = run; run += v; }
    }
    __syncthreads();
    int i = blockIdx.x * blockDim.x + threadIdx.x;
    if (i < N_NODES) {
        int incl = g_scan[i] + pre[i / SCAN_BS];
        int cnt  = g_cnt[i];
        int excl = incl - cnt;
        g_rowptr[i] = excl;
        g_cursor[i] = excl;
        g_inv[i]    = 1.0f / fmaxf((float)cnt, 1.0f);
        if (i == N_NODES - 1) g_rowptr[N_NODES] = incl;
    }
}

// fill CSR; also re-zero g_cnt for the NEXT invocation
__global__ void k_fill(const int* __restrict__ ei, int E) {
    int e = blockIdx.x * blockDim.x + threadIdx.x;
    if (e < N_NODES) g_cnt[e] = 0;
    if (e < E) {
        int src = ei[e];
        int dst = ei[E + e];
        int pos = atomicAdd(&g_cursor[dst], 1);
        g_eidx[pos] = src;
    }
}

// ================= gather-mean (no atomics, fp32, unroll 8 for MLP) ==========
__global__ __launch_bounds__(256)
void k_gather(const float* __restrict__ xext, int layer) {
    const float* feat = (layer == 0) ? xext : g_h1;
    int lane = threadIdx.x & 31;
    int node = blockIdx.x * 8 + (threadIdx.x >> 5);
    if (node >= N_NODES) return;

    int b = g_rowptr[node];
    int e = g_rowptr[node + 1];
    float4 acc = make_float4(0.f, 0.f, 0.f, 0.f);

    int j = b;
    for (; j + 8 <= e; j += 8) {
        int s[8];
        #pragma unroll
        for (int u = 0; u < 8; u++) s[u] = g_eidx[j + u];
        float4 v[8];
        #pragma unroll
        for (int u = 0; u < 8; u++)
            v[u] = __ldg((const float4*)(feat + (size_t)s[u] * D) + lane);
        #pragma unroll
        for (int u = 0; u < 8; u++) {
            acc.x += v[u].x; acc.y += v[u].y;
            acc.z += v[u].z; acc.w += v[u].w;
        }
    }
    for (; j < e; j++) {
        int s = g_eidx[j];
        float4 v = __ldg((const float4*)(feat + (size_t)s * D) + lane);
        acc.x += v.x; acc.y += v.y; acc.z += v.z; acc.w += v.w;
    }
    float sc = g_inv[node];
    acc.x *= sc; acc.y *= sc; acc.z *= sc; acc.w *= sc;
    ((float4*)(g_agg + (size_t)node * D))[lane] = acc;
}

// ---- fp16 helpers ----
__device__ __forceinline__ void pack4_f16_store(__half* base, int off, float4 v) {
    uint32_t p01, p23;
    asm("cvt.rn.f16x2.f32 %0, %1, %2;" : "=r"(p01) : "f"(v.y), "f"(v.x));
    asm("cvt.rn.f16x2.f32 %0, %1, %2;" : "=r"(p23) : "f"(v.w), "f"(v.z));
    *(uint2*)(base + off) = make_uint2(p01, p23);
}

__device__ __forceinline__ void splitB_store(__half* hi, __half* lo, int off, float4 v) {
    float vv[4] = {v.x, v.y, v.z, v.w};
    #pragma unroll
    for (int i = 0; i < 4; i++) {
        __half h = __float2half_rn(vv[i]);
        hi[off + i] = h;
        lo[off + i] = __float2half_rn(vv[i] - __half2float(h));
    }
}

#define MMA_F16(C, A0, A1, A2, A3, B0, B1)                                     \
    asm volatile(                                                              \
        "mma.sync.aligned.m16n8k16.row.col.f32.f16.f16.f32 "                   \
        "{%0,%1,%2,%3}, {%4,%5,%6,%7}, {%8,%9}, {%0,%1,%2,%3};"                \
        : "+f"((C)[0]), "+f"((C)[1]), "+f"((C)[2]), "+f"((C)[3])               \
        : "r"(A0), "r"(A1), "r"(A2), "r"(A3), "r"(B0), "r"(B1))

// ================= fused SAGE layer (fp16 2-term, register-pipelined A) ======
// out = relu( [agg|xroot](50000x256) @ [wl;wr]^T + bl )
__global__ __launch_bounds__(256, 1)
void k_sage_mma(const float* __restrict__ xext,
                const float* __restrict__ wl, const float* __restrict__ bl,
                const float* __restrict__ wr, int layer) {
    extern __shared__ __half sm[];
    __half* sB_hi = sm;                      // 128 * P2
    __half* sB_lo = sB_hi + 128 * P2;        // 128 * P2
    __half* sA    = sB_lo + 128 * P2;        // 32 * P2

    const float* xroot = (layer == 0) ? xext : g_h1;
    float* out = (layer == 0) ? g_h1 : g_h2;

    const int tid  = threadIdx.x;
    const int lane = tid & 31;
    const int w    = tid >> 5;
    const int g    = lane >> 2;
    const int q    = lane & 3;
    const int mr   = (w & 1) * 16;     // warp row offset within 32-row tile
    const int n0   = (w >> 1) * 32;    // warp col offset (4 n8-tiles)

    // stage weights (fp16 hi/lo split): B[n][k], K=256 = [wl | wr]
    for (int idx = tid; idx < 128 * 64; idx += 256) {
        int n  = idx >> 6;
        int k4 = (idx & 63) * 4;
        float4 v = (k4 < 128) ? *(const float4*)&wl[n * 128 + k4]
                              : *(const float4*)&wr[n * 128 + (k4 - 128)];
        splitB_store(sB_hi, sB_lo, n * P2 + k4, v);
    }
    float2 bias_t[4];
    #pragma unroll
    for (int t = 0; t < 4; t++)
        bias_t[t] = *(const float2*)&bl[n0 + t * 8 + q * 2];
    __syncthreads();

    // per-thread staging coordinates (8 chunks of the 32x256 tile)
    int sr[8], sk4[8];
    #pragma unroll
    for (int u = 0; u < 8; u++) {
        int idx = tid + u * 256;
        sr[u]  = idx >> 6;
        sk4[u] = (idx & 63) * 4;
    }

    // prefetch first tile into registers
    float4 pre[8];
    {
        int tile = blockIdx.x;
        #pragma unroll
        for (int u = 0; u < 8; u++) {
            int grow = tile * TM + sr[u];
            float4 v = make_float4(0.f, 0.f, 0.f, 0.f);
            if (tile < NTILES && grow < N_NODES)
                v = (sk4[u] < 128)
                    ? *(const float4*)&g_agg[(size_t)grow * D + sk4[u]]
                    : __ldg((const float4*)&xroot[(size_t)grow * D + (sk4[u] - 128)]);
            pre[u] = v;
        }
    }

    for (int tile = blockIdx.x; tile < NTILES; tile += gridDim.x) {
        // commit prefetched tile to smem
        #pragma unroll
        for (int u = 0; u < 8; u++)
            pack4_f16_store(sA, sr[u] * P2 + sk4[u], pre[u]);
        __syncthreads();

        // prefetch NEXT tile while MMA runs (latency hidden behind tensor work)
        {
            int nt = tile + gridDim.x;
            #pragma unroll
            for (int u = 0; u < 8; u++) {
                int grow = nt * TM + sr[u];
                float4 v = make_float4(0.f, 0.f, 0.f, 0.f);
                if (nt < NTILES && grow < N_NODES)
                    v = (sk4[u] < 128)
                        ? *(const float4*)&g_agg[(size_t)grow * D + sk4[u]]
                        : __ldg((const float4*)&xroot[(size_t)grow * D + (sk4[u] - 128)]);
                pre[u] = v;
            }
        }

        float acc[4][4];
        #pragma unroll
        for (int t = 0; t < 4; t++)
            #pragma unroll
            for (int c = 0; c < 4; c++) acc[t][c] = 0.f;

        #pragma unroll 4
        for (int ks = 0; ks < 16; ks++) {
            const int kk = ks * 16 + q * 2;
            const int ra = (mr + g) * P2;
            uint32_t a0 = *(const uint32_t*)&sA[ra + kk];
            uint32_t a1 = *(const uint32_t*)&sA[ra + 8 * P2 + kk];
            uint32_t a2 = *(const uint32_t*)&sA[ra + kk + 8];
            uint32_t a3 = *(const uint32_t*)&sA[ra + 8 * P2 + kk + 8];
            #pragma unroll
            for (int t = 0; t < 4; t++) {
                const int nb = (n0 + t * 8 + g) * P2;
                uint32_t bh0 = *(const uint32_t*)&sB_hi[nb + kk];
                uint32_t bh1 = *(const uint32_t*)&sB_hi[nb + kk + 8];
                uint32_t bl0 = *(const uint32_t*)&sB_lo[nb + kk];
                uint32_t bl1 = *(const uint32_t*)&sB_lo[nb + kk + 8];
                MMA_F16(acc[t], a0, a1, a2, a3, bh0, bh1);
                MMA_F16(acc[t], a0, a1, a2, a3, bl0, bl1);
            }
        }

        // epilogue: bias + relu, f32 store
        const int row0 = tile * TM;
        const int rA = row0 + mr + g;
        const int rB = rA + 8;
        #pragma unroll
        for (int t = 0; t < 4; t++) {
            const int col0 = n0 + t * 8 + q * 2;
            if (rA < N_NODES) {
                float2 o;
                o.x = fmaxf(acc[t][0] + bias_t[t].x, 0.f);
                o.y = fmaxf(acc[t][1] + bias_t[t].y, 0.f);
                *(float2*)&out[(size_t)rA * D + col0] = o;
            }
            if (rB < N_NODES) {
                float2 o;
                o.x = fmaxf(acc[t][2] + bias_t[t].x, 0.f);
                o.y = fmaxf(acc[t][3] + bias_t[t].y, 0.f);
                *(float2*)&out[(size_t)rB * D + col0] = o;
            }
        }
        __syncthreads();   // all warps done reading sA before next commit
    }
}

// ================= fused MLP head (fp16 2-term) =================
__global__ __launch_bounds__(256, 2)
void k_mlp_mma(const float* __restrict__ mw1, const float* __restrict__ mb1,
               const float* __restrict__ mw2, const float* __restrict__ mb2,
               float* __restrict__ out) {
    extern __shared__ __half sm[];
    __half* sB_hi = sm;                      // 128 * P1
    __half* sB_lo = sB_hi + 128 * P1;
    __half* sA    = sB_lo + 128 * P1;        // 32 * P1
    float* s_part = (float*)(sA + 32 * P1);  // [4][32]

    const int tid  = threadIdx.x;
    const int lane = tid & 31;
    const int w    = tid >> 5;
    const int g    = lane >> 2;
    const int q    = lane & 3;
    const int mr   = (w & 1) * 16;
    const int n0   = (w >> 1) * 32;
    const int grp  = w >> 1;

    for (int idx = tid; idx < 128 * 32; idx += 256) {
        int n  = idx >> 5;
        int k4 = (idx & 31) * 4;
        float4 v = *(const float4*)&mw1[n * 128 + k4];
        splitB_store(sB_hi, sB_lo, n * P1 + k4, v);
    }
    float2 b1_t[4], w2_t[4];
    #pragma unroll
    for (int t = 0; t < 4; t++) {
        b1_t[t] = *(const float2*)&mb1[n0 + t * 8 + q * 2];
        w2_t[t] = *(const float2*)&mw2[n0 + t * 8 + q * 2];
    }
    const float b2 = mb2[0];
    __syncthreads();

    for (int tile = blockIdx.x; tile < NTILES; tile += gridDim.x) {
        const int row0 = tile * TM;
        __syncthreads();
        #pragma unroll 2
        for (int idx = tid; idx < TM * 32; idx += 256) {
            int r  = idx >> 5;
            int k4 = (idx & 31) * 4;
            int grow = row0 + r;
            float4 v = (grow < N_NODES)
                ? *(const float4*)&g_h2[(size_t)grow * D + k4]
                : make_float4(0.f, 0.f, 0.f, 0.f);
            pack4_f16_store(sA, r * P1 + k4, v);
        }
        __syncthreads();

        float acc[4][4];
        #pragma unroll
        for (int t = 0; t < 4; t++)
            #pragma unroll
            for (int c = 0; c < 4; c++) acc[t][c] = 0.f;

        #pragma unroll 4
        for (int ks = 0; ks < 8; ks++) {
            const int kk = ks * 16 + q * 2;
            const int ra = (mr + g) * P1;
            uint32_t a0 = *(const uint32_t*)&sA[ra + kk];
            uint32_t a1 = *(const uint32_t*)&sA[ra + 8 * P1 + kk];
            uint32_t a2 = *(const uint32_t*)&sA[ra + kk + 8];
            uint32_t a3 = *(const uint32_t*)&sA[ra + 8 * P1 + kk + 8];
            #pragma unroll
            for (int t = 0; t < 4; t++) {
                const int nb = (n0 + t * 8 + g) * P1;
                uint32_t bh0 = *(const uint32_t*)&sB_hi[nb + kk];
                uint32_t bh1 = *(const uint32_t*)&sB_hi[nb + kk + 8];
                uint32_t bl0 = *(const uint32_t*)&sB_lo[nb + kk];
                uint32_t bl1 = *(const uint32_t*)&sB_lo[nb + kk + 8];
                MMA_F16(acc[t], a0, a1, a2, a3, bh0, bh1);
                MMA_F16(acc[t], a0, a1, a2, a3, bl0, bl1);
            }
        }

        float pg = 0.f, pg8 = 0.f;
        #pragma unroll
        for (int t = 0; t < 4; t++) {
            pg  += fmaxf(acc[t][0] + b1_t[t].x, 0.f) * w2_t[t].x
                 + fmaxf(acc[t][1] + b1_t[t].y, 0.f) * w2_t[t].y;
            pg8 += fmaxf(acc[t][2] + b1_t[t].x, 0.f) * w2_t[t].x
                 + fmaxf(acc[t][3] + b1_t[t].y, 0.f) * w2_t[t].y;
        }
        pg  += __shfl_xor_sync(0xffffffffu, pg, 1);
        pg  += __shfl_xor_sync(0xffffffffu, pg, 2);
        pg8 += __shfl_xor_sync(0xffffffffu, pg8, 1);
        pg8 += __shfl_xor_sync(0xffffffffu, pg8, 2);
        if (q == 0) {
            s_part[grp * 32 + mr + g]     = pg;
            s_part[grp * 32 + mr + g + 8] = pg8;
        }
        __syncthreads();
        if (tid < 32) {
            int grow = row0 + tid;
            if (grow < N_NODES) {
                out[grow] = s_part[tid] + s_part[32 + tid] + s_part[64 + tid]
                          + s_part[96 + tid] + b2;
            }
        }
    }
}

extern "C" void kernel_launch(void* const* d_in, const int* in_sizes, int n_in,
                              void* d_out, int out_size) {
    const float* x   = (const float*)d_in[0];
    const int*   ei  = (const int*)d_in[1];      // int32 (JAX x64 disabled)
    const float* w1l = (const float*)d_in[2];
    const float* b1l = (const float*)d_in[3];
    const float* w1r = (const float*)d_in[4];
    const float* w2l = (const float*)d_in[5];
    const float* b2l = (const float*)d_in[6];
    const float* w2r = (const float*)d_in[7];
    const float* mw1 = (const float*)d_in[8];
    const float* mb1 = (const float*)d_in[9];
    const float* mw2 = (const float*)d_in[10];
    const float* mb2 = (const float*)d_in[11];
    float* out = (float*)d_out;
    const int E = in_sizes[1] / 2;

    const int sage_smem = (2 * 128 * P2 + 32 * P2) * (int)sizeof(__half);  // 152064
    const int mlp_smem  = (2 * 128 * P1 + 32 * P1) * (int)sizeof(__half)
                        + 4 * 32 * (int)sizeof(float);                     // 78848
    cudaFuncSetAttribute(k_sage_mma, cudaFuncAttributeMaxDynamicSharedMemorySize, sage_smem);
    cudaFuncSetAttribute(k_mlp_mma,  cudaFuncAttributeMaxDynamicSharedMemorySize, mlp_smem);

    // ---- CSR build (g_cnt is zero at entry: zero-init + k_fill re-zero) ----
    k_count<<<(E + 255) / 256, 256>>>(ei, E);
    k_scan1<<<SCAN_NB, SCAN_BS>>>();
    k_scan23<<<(N_NODES + 255) / 256, 256>>>();
    k_fill<<<(E + 255) / 256, 256>>>(ei, E);

    const int gat_blocks = (N_NODES + 7) / 8;

    // ---- layer 1 ----
    k_gather<<<gat_blocks, 256>>>(x, 0);
    k_sage_mma<<<148, 256, sage_smem>>>(x, w1l, b1l, w1r, 0);

    // ---- layer 2 ----
    k_gather<<<gat_blocks, 256>>>(x, 1);
    k_sage_mma<<<148, 256, sage_smem>>>(x, w2l, b2l, w2r, 1);

    // ---- MLP head ----
    k_mlp_mma<<<296, 256, mlp_smem>>>(mw1, mb1, mw2, mb2, out);
}

// round 17
// speedup vs baseline: 1.5787x; 1.0302x over previous
#include <cuda_runtime.h>
#include <cuda_fp16.h>
#include <cstdint>

#define N_NODES 50000
#define D 128
#define TM 32
#define NTILES ((N_NODES + TM - 1) / TM)           // 1563
#define SCAN_BS 1024
#define SCAN_NB ((N_NODES + SCAN_BS - 1) / SCAN_BS)   // 49
#define P2 264   // padded row stride (fp16 elems) for K=256 tiles
#define P1 136   // padded row stride for K=128 tiles

// ---- scratch (allocation-free: __device__ globals; zero-initialized) ----
__device__ float g_agg[(size_t)N_NODES * D];
__device__ float g_h1 [(size_t)N_NODES * D];
__device__ float g_h2 [(size_t)N_NODES * D];
__device__ float g_inv[N_NODES];
__device__ int   g_cnt[N_NODES];        // zero at entry; re-zeroed by k_fill
__device__ int   g_scan[N_NODES];
__device__ int   g_rowptr[N_NODES + 1];
__device__ int   g_cursor[N_NODES];
__device__ int   g_eidx[1700000];
__device__ int   g_bsum[SCAN_NB];

// ================= CSR build =================
__global__ void k_count(const int* __restrict__ ei, int E) {
    int e = blockIdx.x * blockDim.x + threadIdx.x;
    if (e < E) atomicAdd(&g_cnt[ei[E + e]], 1);
}

__global__ void k_scan1() {
    __shared__ int sh[SCAN_BS];
    int i = blockIdx.x * SCAN_BS + threadIdx.x;
    int v = (i < N_NODES) ? g_cnt[i] : 0;
    sh[threadIdx.x] = v;
    __syncthreads();
    for (int off = 1; off < SCAN_BS; off <<= 1) {
        int t = (threadIdx.x >= off) ? sh[threadIdx.x - off] : 0;
        __syncthreads();
        sh[threadIdx.x] += t;
        __syncthreads();
    }
    if (i < N_NODES) g_scan[i] = sh[threadIdx.x];
    if (threadIdx.x == SCAN_BS - 1) g_bsum[blockIdx.x] = sh[threadIdx.x];
}

__global__ void k_scan23() {
    __shared__ int pre[SCAN_NB];
    if (threadIdx.x < SCAN_NB) pre[threadIdx.x] = g_bsum[threadIdx.x];
    __syncthreads();
    if (threadIdx.x == 0) {
        int run = 0;
        #pragma unroll 1
        for (int b = 0; b < SCAN_NB; b++) { int v = pre[b]; pre[b] = run; run += v; }
    }
    __syncthreads();
    int i = blockIdx.x * blockDim.x + threadIdx.x;
    if (i < N_NODES) {
        int incl = g_scan[i] + pre[i / SCAN_BS];
        int cnt  = g_cnt[i];
        int excl = incl - cnt;
        g_rowptr[i] = excl;
        g_cursor[i] = excl;
        g_inv[i]    = 1.0f / fmaxf((float)cnt, 1.0f);
        if (i == N_NODES - 1) g_rowptr[N_NODES] = incl;
    }
}

// fill CSR; also re-zero g_cnt for the NEXT invocation
__global__ void k_fill(const int* __restrict__ ei, int E) {
    int e = blockIdx.x * blockDim.x + threadIdx.x;
    if (e < N_NODES) g_cnt[e] = 0;
    if (e < E) {
        int src = ei[e];
        int dst = ei[E + e];
        int pos = atomicAdd(&g_cursor[dst], 1);
        g_eidx[pos] = src;
    }
}

// ================= gather-mean (no atomics, fp32, 16 loads in flight) ========
__global__ __launch_bounds__(256)
void k_gather(const float* __restrict__ xext, int layer) {
    const float* feat = (layer == 0) ? xext : g_h1;
    int lane = threadIdx.x & 31;
    int node = blockIdx.x * 8 + (threadIdx.x >> 5);
    if (node >= N_NODES) return;

    int b = g_rowptr[node];
    int e = g_rowptr[node + 1];
    float4 acc = make_float4(0.f, 0.f, 0.f, 0.f);

    int j = b;
    for (; j + 16 <= e; j += 16) {
        int s[16];
        #pragma unroll
        for (int u = 0; u < 16; u++) s[u] = g_eidx[j + u];
        float4 v[16];
        #pragma unroll
        for (int u = 0; u < 16; u++)
            v[u] = __ldg((const float4*)(feat + (size_t)s[u] * D) + lane);
        #pragma unroll
        for (int u = 0; u < 16; u++) {
            acc.x += v[u].x; acc.y += v[u].y;
            acc.z += v[u].z; acc.w += v[u].w;
        }
    }
    for (; j + 4 <= e; j += 4) {
        int s[4];
        #pragma unroll
        for (int u = 0; u < 4; u++) s[u] = g_eidx[j + u];
        float4 v[4];
        #pragma unroll
        for (int u = 0; u < 4; u++)
            v[u] = __ldg((const float4*)(feat + (size_t)s[u] * D) + lane);
        #pragma unroll
        for (int u = 0; u < 4; u++) {
            acc.x += v[u].x; acc.y += v[u].y;
            acc.z += v[u].z; acc.w += v[u].w;
        }
    }
    for (; j < e; j++) {
        int s = g_eidx[j];
        float4 v = __ldg((const float4*)(feat + (size_t)s * D) + lane);
        acc.x += v.x; acc.y += v.y; acc.z += v.z; acc.w += v.w;
    }
    float sc = g_inv[node];
    acc.x *= sc; acc.y *= sc; acc.z *= sc; acc.w *= sc;
    ((float4*)(g_agg + (size_t)node * D))[lane] = acc;
}

// ---- fp16 helpers ----
__device__ __forceinline__ void pack4_f16_store(__half* base, int off, float4 v) {
    uint32_t p01, p23;
    asm("cvt.rn.f16x2.f32 %0, %1, %2;" : "=r"(p01) : "f"(v.y), "f"(v.x));
    asm("cvt.rn.f16x2.f32 %0, %1, %2;" : "=r"(p23) : "f"(v.w), "f"(v.z));
    *(uint2*)(base + off) = make_uint2(p01, p23);
}

__device__ __forceinline__ void splitB_store(__half* hi, __half* lo, int off, float4 v) {
    float vv[4] = {v.x, v.y, v.z, v.w};
    #pragma unroll
    for (int i = 0; i < 4; i++) {
        __half h = __float2half_rn(vv[i]);
        hi[off + i] = h;
        lo[off + i] = __float2half_rn(vv[i] - __half2float(h));
    }
}

#define MMA_F16(C, A0, A1, A2, A3, B0, B1)                                     \
    asm volatile(                                                              \
        "mma.sync.aligned.m16n8k16.row.col.f32.f16.f16.f32 "                   \
        "{%0,%1,%2,%3}, {%4,%5,%6,%7}, {%8,%9}, {%0,%1,%2,%3};"                \
        : "+f"((C)[0]), "+f"((C)[1]), "+f"((C)[2]), "+f"((C)[3])               \
        : "r"(A0), "r"(A1), "r"(A2), "r"(A3), "r"(B0), "r"(B1))

// ================= fused SAGE layer (fp16 2-term, register-pipelined A) ======
__global__ __launch_bounds__(256, 1)
void k_sage_mma(const float* __restrict__ xext,
                const float* __restrict__ wl, const float* __restrict__ bl,
                const float* __restrict__ wr, int layer) {
    extern __shared__ __half sm[];
    __half* sB_hi = sm;                      // 128 * P2
    __half* sB_lo = sB_hi + 128 * P2;        // 128 * P2
    __half* sA    = sB_lo + 128 * P2;        // 32 * P2

    const float* xroot = (layer == 0) ? xext : g_h1;
    float* out = (layer == 0) ? g_h1 : g_h2;

    const int tid  = threadIdx.x;
    const int lane = tid & 31;
    const int w    = tid >> 5;
    const int g    = lane >> 2;
    const int q    = lane & 3;
    const int mr   = (w & 1) * 16;
    const int n0   = (w >> 1) * 32;

    for (int idx = tid; idx < 128 * 64; idx += 256) {
        int n  = idx >> 6;
        int k4 = (idx & 63) * 4;
        float4 v = (k4 < 128) ? *(const float4*)&wl[n * 128 + k4]
                              : *(const float4*)&wr[n * 128 + (k4 - 128)];
        splitB_store(sB_hi, sB_lo, n * P2 + k4, v);
    }
    float2 bias_t[4];
    #pragma unroll
    for (int t = 0; t < 4; t++)
        bias_t[t] = *(const float2*)&bl[n0 + t * 8 + q * 2];
    __syncthreads();

    int sr[8], sk4[8];
    #pragma unroll
    for (int u = 0; u < 8; u++) {
        int idx = tid + u * 256;
        sr[u]  = idx >> 6;
        sk4[u] = (idx & 63) * 4;
    }

    float4 pre[8];
    {
        int tile = blockIdx.x;
        #pragma unroll
        for (int u = 0; u < 8; u++) {
            int grow = tile * TM + sr[u];
            float4 v = make_float4(0.f, 0.f, 0.f, 0.f);
            if (tile < NTILES && grow < N_NODES)
                v = (sk4[u] < 128)
                    ? *(const float4*)&g_agg[(size_t)grow * D + sk4[u]]
                    : __ldg((const float4*)&xroot[(size_t)grow * D + (sk4[u] - 128)]);
            pre[u] = v;
        }
    }

    for (int tile = blockIdx.x; tile < NTILES; tile += gridDim.x) {
        #pragma unroll
        for (int u = 0; u < 8; u++)
            pack4_f16_store(sA, sr[u] * P2 + sk4[u], pre[u]);
        __syncthreads();

        {
            int nt = tile + gridDim.x;
            #pragma unroll
            for (int u = 0; u < 8; u++) {
                int grow = nt * TM + sr[u];
                float4 v = make_float4(0.f, 0.f, 0.f, 0.f);
                if (nt < NTILES && grow < N_NODES)
                    v = (sk4[u] < 128)
                        ? *(const float4*)&g_agg[(size_t)grow * D + sk4[u]]
                        : __ldg((const float4*)&xroot[(size_t)grow * D + (sk4[u] - 128)]);
                pre[u] = v;
            }
        }

        float acc[4][4];
        #pragma unroll
        for (int t = 0; t < 4; t++)
            #pragma unroll
            for (int c = 0; c < 4; c++) acc[t][c] = 0.f;

        #pragma unroll 4
        for (int ks = 0; ks < 16; ks++) {
            const int kk = ks * 16 + q * 2;
            const int ra = (mr + g) * P2;
            uint32_t a0 = *(const uint32_t*)&sA[ra + kk];
            uint32_t a1 = *(const uint32_t*)&sA[ra + 8 * P2 + kk];
            uint32_t a2 = *(const uint32_t*)&sA[ra + kk + 8];
            uint32_t a3 = *(const uint32_t*)&sA[ra + 8 * P2 + kk + 8];
            #pragma unroll
            for (int t = 0; t < 4; t++) {
                const int nb = (n0 + t * 8 + g) * P2;
                uint32_t bh0 = *(const uint32_t*)&sB_hi[nb + kk];
                uint32_t bh1 = *(const uint32_t*)&sB_hi[nb + kk + 8];
                uint32_t bl0 = *(const uint32_t*)&sB_lo[nb + kk];
                uint32_t bl1 = *(const uint32_t*)&sB_lo[nb + kk + 8];
                MMA_F16(acc[t], a0, a1, a2, a3, bh0, bh1);
                MMA_F16(acc[t], a0, a1, a2, a3, bl0, bl1);
            }
        }

        const int row0 = tile * TM;
        const int rA = row0 + mr + g;
        const int rB = rA + 8;
        #pragma unroll
        for (int t = 0; t < 4; t++) {
            const int col0 = n0 + t * 8 + q * 2;
            if (rA < N_NODES) {
                float2 o;
                o.x = fmaxf(acc[t][0] + bias_t[t].x, 0.f);
                o.y = fmaxf(acc[t][1] + bias_t[t].y, 0.f);
                *(float2*)&out[(size_t)rA * D + col0] = o;
            }
            if (rB < N_NODES) {
                float2 o;
                o.x = fmaxf(acc[t][2] + bias_t[t].x, 0.f);
                o.y = fmaxf(acc[t][3] + bias_t[t].y, 0.f);
                *(float2*)&out[(size_t)rB * D + col0] = o;
            }
        }
        __syncthreads();
    }
}

// ================= fused MLP head (fp16 2-term, register-pipelined A) ========
__global__ __launch_bounds__(256, 2)
void k_mlp_mma(const float* __restrict__ mw1, const float* __restrict__ mb1,
               const float* __restrict__ mw2, const float* __restrict__ mb2,
               float* __restrict__ out) {
    extern __shared__ __half sm[];
    __half* sB_hi = sm;                      // 128 * P1
    __half* sB_lo = sB_hi + 128 * P1;
    __half* sA    = sB_lo + 128 * P1;        // 32 * P1
    float* s_part = (float*)(sA + 32 * P1);  // [4][32]

    const int tid  = threadIdx.x;
    const int lane = tid & 31;
    const int w    = tid >> 5;
    const int g    = lane >> 2;
    const int q    = lane & 3;
    const int mr   = (w & 1) * 16;
    const int n0   = (w >> 1) * 32;
    const int grp  = w >> 1;

    for (int idx = tid; idx < 128 * 32; idx += 256) {
        int n  = idx >> 5;
        int k4 = (idx & 31) * 4;
        float4 v = *(const float4*)&mw1[n * 128 + k4];
        splitB_store(sB_hi, sB_lo, n * P1 + k4, v);
    }
    float2 b1_t[4], w2_t[4];
    #pragma unroll
    for (int t = 0; t < 4; t++) {
        b1_t[t] = *(const float2*)&mb1[n0 + t * 8 + q * 2];
        w2_t[t] = *(const float2*)&mw2[n0 + t * 8 + q * 2];
    }
    const float b2 = mb2[0];
    __syncthreads();

    int sr[4], sk4[4];
    #pragma unroll
    for (int u = 0; u < 4; u++) {
        int idx = tid + u * 256;
        sr[u]  = idx >> 5;
        sk4[u] = (idx & 31) * 4;
    }

    float4 pre[4];
    {
        int tile = blockIdx.x;
        #pragma unroll
        for (int u = 0; u < 4; u++) {
            int grow = tile * TM + sr[u];
            pre[u] = (tile < NTILES && grow < N_NODES)
                ? *(const float4*)&g_h2[(size_t)grow * D + sk4[u]]
                : make_float4(0.f, 0.f, 0.f, 0.f);
        }
    }

    for (int tile = blockIdx.x; tile < NTILES; tile += gridDim.x) {
        #pragma unroll
        for (int u = 0; u < 4; u++)
            pack4_f16_store(sA, sr[u] * P1 + sk4[u], pre[u]);
        __syncthreads();

        {
            int nt = tile + gridDim.x;
            #pragma unroll
            for (int u = 0; u < 4; u++) {
                int grow = nt * TM + sr[u];
                pre[u] = (nt < NTILES && grow < N_NODES)
                    ? *(const float4*)&g_h2[(size_t)grow * D + sk4[u]]
                    : make_float4(0.f, 0.f, 0.f, 0.f);
            }
        }

        float acc[4][4];
        #pragma unroll
        for (int t = 0; t < 4; t++)
            #pragma unroll
            for (int c = 0; c < 4; c++) acc[t][c] = 0.f;

        #pragma unroll 4
        for (int ks = 0; ks < 8; ks++) {
            const int kk = ks * 16 + q * 2;
            const int ra = (mr + g) * P1;
            uint32_t a0 = *(const uint32_t*)&sA[ra + kk];
            uint32_t a1 = *(const uint32_t*)&sA[ra + 8 * P1 + kk];
            uint32_t a2 = *(const uint32_t*)&sA[ra + kk + 8];
            uint32_t a3 = *(const uint32_t*)&sA[ra + 8 * P1 + kk + 8];
            #pragma unroll
            for (int t = 0; t < 4; t++) {
                const int nb = (n0 + t * 8 + g) * P1;
                uint32_t bh0 = *(const uint32_t*)&sB_hi[nb + kk];
                uint32_t bh1 = *(const uint32_t*)&sB_hi[nb + kk + 8];
                uint32_t bl0 = *(const uint32_t*)&sB_lo[nb + kk];
                uint32_t bl1 = *(const uint32_t*)&sB_lo[nb + kk + 8];
                MMA_F16(acc[t], a0, a1, a2, a3, bh0, bh1);
                MMA_F16(acc[t], a0, a1, a2, a3, bl0, bl1);
            }
        }

        const int row0 = tile * TM;
        float pg = 0.f, pg8 = 0.f;
        #pragma unroll
        for (int t = 0; t < 4; t++) {
            pg  += fmaxf(acc[t][0] + b1_t[t].x, 0.f) * w2_t[t].x
                 + fmaxf(acc[t][1] + b1_t[t].y, 0.f) * w2_t[t].y;
            pg8 += fmaxf(acc[t][2] + b1_t[t].x, 0.f) * w2_t[t].x
                 + fmaxf(acc[t][3] + b1_t[t].y, 0.f) * w2_t[t].y;
        }
        pg  += __shfl_xor_sync(0xffffffffu, pg, 1);
        pg  += __shfl_xor_sync(0xffffffffu, pg, 2);
        pg8 += __shfl_xor_sync(0xffffffffu, pg8, 1);
        pg8 += __shfl_xor_sync(0xffffffffu, pg8, 2);
        if (q == 0) {
            s_part[grp * 32 + mr + g]     = pg;
            s_part[grp * 32 + mr + g + 8] = pg8;
        }
        __syncthreads();
        if (tid < 32) {
            int grow = row0 + tid;
            if (grow < N_NODES) {
                out[grow] = s_part[tid] + s_part[32 + tid] + s_part[64 + tid]
                          + s_part[96 + tid] + b2;
            }
        }
        __syncthreads();
    }
}

extern "C" void kernel_launch(void* const* d_in, const int* in_sizes, int n_in,
                              void* d_out, int out_size) {
    const float* x   = (const float*)d_in[0];
    const int*   ei  = (const int*)d_in[1];      // int32 (JAX x64 disabled)
    const float* w1l = (const float*)d_in[2];
    const float* b1l = (const float*)d_in[3];
    const float* w1r = (const float*)d_in[4];
    const float* w2l = (const float*)d_in[5];
    const float* b2l = (const float*)d_in[6];
    const float* w2r = (const float*)d_in[7];
    const float* mw1 = (const float*)d_in[8];
    const float* mb1 = (const float*)d_in[9];
    const float* mw2 = (const float*)d_in[10];
    const float* mb2 = (const float*)d_in[11];
    float* out = (float*)d_out;
    const int E = in_sizes[1] / 2;

    const int sage_smem = (2 * 128 * P2 + 32 * P2) * (int)sizeof(__half);  // 152064
    const int mlp_smem  = (2 * 128 * P1 + 32 * P1) * (int)sizeof(__half)
                        + 4 * 32 * (int)sizeof(float);                     // 78848
    cudaFuncSetAttribute(k_sage_mma, cudaFuncAttributeMaxDynamicSharedMemorySize, sage_smem);
    cudaFuncSetAttribute(k_mlp_mma,  cudaFuncAttributeMaxDynamicSharedMemorySize, mlp_smem);

    // ---- CSR build (g_cnt is zero at entry: zero-init + k_fill re-zero) ----
    k_count<<<(E + 255) / 256, 256>>>(ei, E);
    k_scan1<<<SCAN_NB, SCAN_BS>>>();
    k_scan23<<<(N_NODES + 255) / 256, 256>>>();
    k_fill<<<(E + 255) / 256, 256>>>(ei, E);

    const int gat_blocks = (N_NODES + 7) / 8;

    // ---- layer 1 ----
    k_gather<<<gat_blocks, 256>>>(x, 0);
    k_sage_mma<<<148, 256, sage_smem>>>(x, w1l, b1l, w1r, 0);

    // ---- layer 2 ----
    k_gather<<<gat_blocks, 256>>>(x, 1);
    k_sage_mma<<<148, 256, sage_smem>>>(x, w2l, b2l, w2r, 1);

    // ---- MLP head ----
    k_mlp_mma<<<296, 256, mlp_smem>>>(mw1, mb1, mw2, mb2, out);
}